// round 1
// baseline (speedup 1.0000x reference)
#include <cuda_runtime.h>

#define BB 2
#define SS 2048
#define DD 1024
#define HH 16
#define HD 64
#define MM (BB * SS)   // 4096 rows

// Scratch (allocation-free rule: __device__ globals)
__device__ __align__(16) float g_Q[BB * SS * DD];   // (B,H,S,HD)
__device__ __align__(16) float g_K[BB * SS * DD];   // (B,H,S,HD)
__device__ __align__(16) float g_V[BB * SS * DD];   // (B,H,S,HD)
__device__ __align__(16) float g_A[BB * SS * DD];   // attn out (B,S,D)

// ---------------------------------------------------------------------------
// C[m,n] = sum_k A[m,k] * W[n,k] + bias[n]
// A: (M=4096, K=1024) row-major, W: (N=1024, K=1024) row-major (i.e. X @ W^T)
// head_split=1: write C into (B,H,S,HD) layout; else plain (M,N).
// 128x128 tile, BK=8, 256 threads, 8x8 per-thread microtile.
// ---------------------------------------------------------------------------
__global__ __launch_bounds__(256) void sgemm_bias(
    const float* __restrict__ A,
    const float* __restrict__ W,
    const float* __restrict__ bias,
    float* __restrict__ C,
    int head_split)
{
    const int K = DD;
    __shared__ float As[8][128];
    __shared__ float Ws[8][128];

    int tid = threadIdx.x;
    int bm = blockIdx.y * 128;
    int bn = blockIdx.x * 128;

    int lrow = tid >> 1;          // 0..127
    int lcol = (tid & 1) * 4;     // 0 or 4
    int tx = tid & 15;            // 0..15 -> n microtile
    int ty = tid >> 4;            // 0..15 -> m microtile

    float acc[8][8];
#pragma unroll
    for (int i = 0; i < 8; i++)
#pragma unroll
        for (int j = 0; j < 8; j++) acc[i][j] = 0.f;

    const float* Aptr = A + (size_t)(bm + lrow) * K + lcol;
    const float* Wptr = W + (size_t)(bn + lrow) * K + lcol;

    for (int k0 = 0; k0 < K; k0 += 8) {
        float4 av = *(const float4*)(Aptr + k0);
        float4 wv = *(const float4*)(Wptr + k0);
        __syncthreads();
        As[lcol + 0][lrow] = av.x; As[lcol + 1][lrow] = av.y;
        As[lcol + 2][lrow] = av.z; As[lcol + 3][lrow] = av.w;
        Ws[lcol + 0][lrow] = wv.x; Ws[lcol + 1][lrow] = wv.y;
        Ws[lcol + 2][lrow] = wv.z; Ws[lcol + 3][lrow] = wv.w;
        __syncthreads();
#pragma unroll
        for (int kk = 0; kk < 8; kk++) {
            float ar[8], wr[8];
#pragma unroll
            for (int i = 0; i < 8; i++) ar[i] = As[kk][ty * 8 + i];
#pragma unroll
            for (int j = 0; j < 8; j++) wr[j] = Ws[kk][tx * 8 + j];
#pragma unroll
            for (int i = 0; i < 8; i++)
#pragma unroll
                for (int j = 0; j < 8; j++)
                    acc[i][j] += ar[i] * wr[j];
        }
    }

#pragma unroll
    for (int i = 0; i < 8; i++) {
        int m = bm + ty * 8 + i;
#pragma unroll
        for (int j = 0; j < 8; j++) {
            int n = bn + tx * 8 + j;
            float v = acc[i][j] + bias[n];
            if (head_split) {
                int b = m >> 11;          // m / SS
                int s = m & (SS - 1);
                int h = n >> 6;           // n / HD
                int hd = n & (HD - 1);
                C[(((size_t)(b * HH + h)) * SS + s) * HD + hd] = v;
            } else {
                C[(size_t)m * DD + n] = v;
            }
        }
    }
}

// ---------------------------------------------------------------------------
// Flash attention, fp32. One thread per query row; 128 q-rows per block.
// K/V tiles (64 x 64) staged in smem; all threads read the SAME smem row
// per step -> broadcast LDS -> FFMA-bound.
// mask (B,1,S) applies to key positions: additive bias 0 / -1e9.
// ---------------------------------------------------------------------------
__global__ __launch_bounds__(128) void attn_kernel(
    const float* __restrict__ Q,
    const float* __restrict__ Kt,
    const float* __restrict__ Vt,
    const int* __restrict__ mask,
    float* __restrict__ Out)
{
    __shared__ float Ks[64][64];
    __shared__ float Vs[64][64];
    __shared__ float bsm[64];

    int b = blockIdx.z, h = blockIdx.y;
    int s = blockIdx.x * 128 + threadIdx.x;

    const float* Qr = Q + (((size_t)(b * HH + h)) * SS + s) * HD;
    const float* Kb = Kt + ((size_t)(b * HH + h)) * SS * HD;
    const float* Vb = Vt + ((size_t)(b * HH + h)) * SS * HD;
    const int* mb = mask + b * SS;

    float q[64];
#pragma unroll
    for (int i = 0; i < 16; i++) {
        float4 t = *(const float4*)(Qr + i * 4);
        q[i * 4 + 0] = t.x; q[i * 4 + 1] = t.y;
        q[i * 4 + 2] = t.z; q[i * 4 + 3] = t.w;
    }

    float acc[64];
#pragma unroll
    for (int d = 0; d < 64; d++) acc[d] = 0.f;
    float mrun = -1e30f;
    float l = 0.f;

    for (int kt = 0; kt < SS; kt += 64) {
        __syncthreads();
        // load K/V tile (64 rows x 64) cooperatively
        for (int idx = threadIdx.x; idx < 64 * 16; idx += 128) {
            int r = idx >> 4;
            int c = (idx & 15) * 4;
            *(float4*)&Ks[r][c] = *(const float4*)(Kb + (size_t)(kt + r) * HD + c);
            *(float4*)&Vs[r][c] = *(const float4*)(Vb + (size_t)(kt + r) * HD + c);
        }
        if (threadIdx.x < 64)
            bsm[threadIdx.x] = mb[kt + threadIdx.x] ? 0.f : -1e9f;
        __syncthreads();

#pragma unroll 1
        for (int c = 0; c < 4; c++) {
            float sreg[16];
            float cmax = -1e30f;
#pragma unroll
            for (int j = 0; j < 16; j++) {
                int kr = c * 16 + j;
                float d0 = 0.f, d1 = 0.f, d2 = 0.f, d3 = 0.f;
#pragma unroll
                for (int t = 0; t < 16; t++) {
                    float4 kv = *(const float4*)&Ks[kr][t * 4];
                    d0 += q[t * 4 + 0] * kv.x;
                    d1 += q[t * 4 + 1] * kv.y;
                    d2 += q[t * 4 + 2] * kv.z;
                    d3 += q[t * 4 + 3] * kv.w;
                }
                float sc = ((d0 + d1) + (d2 + d3)) * 0.125f + bsm[kr];
                sreg[j] = sc;
                cmax = fmaxf(cmax, sc);
            }
            float nm = fmaxf(mrun, cmax);
            float corr = __expf(mrun - nm);
            float psum = 0.f;
#pragma unroll
            for (int j = 0; j < 16; j++) {
                float p = __expf(sreg[j] - nm);
                sreg[j] = p;
                psum += p;
            }
            l = l * corr + psum;
#pragma unroll
            for (int d = 0; d < 64; d++) acc[d] *= corr;
#pragma unroll
            for (int j = 0; j < 16; j++) {
                int kr = c * 16 + j;
                float p = sreg[j];
#pragma unroll
                for (int t = 0; t < 16; t++) {
                    float4 vv = *(const float4*)&Vs[kr][t * 4];
                    acc[t * 4 + 0] += p * vv.x;
                    acc[t * 4 + 1] += p * vv.y;
                    acc[t * 4 + 2] += p * vv.z;
                    acc[t * 4 + 3] += p * vv.w;
                }
            }
            mrun = nm;
        }
    }

    float inv = 1.0f / l;
    float* Or = Out + ((size_t)(b * SS + s)) * DD + h * HD;
#pragma unroll
    for (int t = 0; t < 16; t++) {
        float4 o;
        o.x = acc[t * 4 + 0] * inv;
        o.y = acc[t * 4 + 1] * inv;
        o.z = acc[t * 4 + 2] * inv;
        o.w = acc[t * 4 + 3] * inv;
        *(float4*)(Or + t * 4) = o;
    }
}

// ---------------------------------------------------------------------------
extern "C" void kernel_launch(void* const* d_in, const int* in_sizes, int n_in,
                              void* d_out, int out_size)
{
    const float* xq = (const float*)d_in[0];
    const float* xk = (const float*)d_in[1];
    const float* xv = (const float*)d_in[2];
    const int*   mask = (const int*)d_in[3];
    const float* wq = (const float*)d_in[4];
    const float* bq = (const float*)d_in[5];
    const float* wk = (const float*)d_in[6];
    const float* bk = (const float*)d_in[7];
    const float* wv = (const float*)d_in[8];
    const float* bv = (const float*)d_in[9];
    const float* wo = (const float*)d_in[10];
    const float* bo = (const float*)d_in[11];
    float* out = (float*)d_out;

    float *Qp, *Kp, *Vp, *Ap;
    cudaGetSymbolAddress((void**)&Qp, g_Q);
    cudaGetSymbolAddress((void**)&Kp, g_K);
    cudaGetSymbolAddress((void**)&Vp, g_V);
    cudaGetSymbolAddress((void**)&Ap, g_A);

    dim3 ggrid(DD / 128, MM / 128);   // (8, 32)
    sgemm_bias<<<ggrid, 256>>>(xq, wq, bq, Qp, 1);
    sgemm_bias<<<ggrid, 256>>>(xk, wk, bk, Kp, 1);
    sgemm_bias<<<ggrid, 256>>>(xv, wv, bv, Vp, 1);

    attn_kernel<<<dim3(SS / 128, HH, BB), 128>>>(Qp, Kp, Vp, mask, Ap);

    sgemm_bias<<<ggrid, 256>>>(Ap, wo, bo, out, 0);
}

// round 3
// speedup vs baseline: 1.0819x; 1.0819x over previous
#include <cuda_runtime.h>

#define BB 2
#define SS 2048
#define DD 1024
#define HH 16
#define HD 64
#define MM (BB * SS)   // 4096 rows

// Scratch (allocation-free rule: __device__ globals)
__device__ __align__(16) float g_Q[BB * SS * DD];   // (B,H,S,HD)
__device__ __align__(16) float g_K[BB * SS * DD];   // (B,H,S,HD)
__device__ __align__(16) float g_V[BB * SS * DD];   // (B,H,S,HD)
__device__ __align__(16) float g_A[BB * SS * DD];   // attn out (B,S,D)

// ---------------------------------------------------------------------------
// C[m,n] = sum_k A[m,k] * W[n,k] + bias[n]   (unchanged from round 1)
// ---------------------------------------------------------------------------
__global__ __launch_bounds__(256) void sgemm_bias(
    const float* __restrict__ A,
    const float* __restrict__ W,
    const float* __restrict__ bias,
    float* __restrict__ C,
    int head_split)
{
    const int K = DD;
    __shared__ float As[8][128];
    __shared__ float Ws[8][128];

    int tid = threadIdx.x;
    int bm = blockIdx.y * 128;
    int bn = blockIdx.x * 128;

    int lrow = tid >> 1;
    int lcol = (tid & 1) * 4;
    int tx = tid & 15;
    int ty = tid >> 4;

    float acc[8][8];
#pragma unroll
    for (int i = 0; i < 8; i++)
#pragma unroll
        for (int j = 0; j < 8; j++) acc[i][j] = 0.f;

    const float* Aptr = A + (size_t)(bm + lrow) * K + lcol;
    const float* Wptr = W + (size_t)(bn + lrow) * K + lcol;

    for (int k0 = 0; k0 < K; k0 += 8) {
        float4 av = *(const float4*)(Aptr + k0);
        float4 wv = *(const float4*)(Wptr + k0);
        __syncthreads();
        As[lcol + 0][lrow] = av.x; As[lcol + 1][lrow] = av.y;
        As[lcol + 2][lrow] = av.z; As[lcol + 3][lrow] = av.w;
        Ws[lcol + 0][lrow] = wv.x; Ws[lcol + 1][lrow] = wv.y;
        Ws[lcol + 2][lrow] = wv.z; Ws[lcol + 3][lrow] = wv.w;
        __syncthreads();
#pragma unroll
        for (int kk = 0; kk < 8; kk++) {
            float ar[8], wr[8];
#pragma unroll
            for (int i = 0; i < 8; i++) ar[i] = As[kk][ty * 8 + i];
#pragma unroll
            for (int j = 0; j < 8; j++) wr[j] = Ws[kk][tx * 8 + j];
#pragma unroll
            for (int i = 0; i < 8; i++)
#pragma unroll
                for (int j = 0; j < 8; j++)
                    acc[i][j] += ar[i] * wr[j];
        }
    }

#pragma unroll
    for (int i = 0; i < 8; i++) {
        int m = bm + ty * 8 + i;
#pragma unroll
        for (int j = 0; j < 8; j++) {
            int n = bn + tx * 8 + j;
            float v = acc[i][j] + bias[n];
            if (head_split) {
                int b = m >> 11;
                int s = m & (SS - 1);
                int h = n >> 6;
                int hd = n & (HD - 1);
                C[(((size_t)(b * HH + h)) * SS + s) * HD + hd] = v;
            } else {
                C[(size_t)m * DD + n] = v;
            }
        }
    }
}

// ---------------------------------------------------------------------------
// Block-tiled flash attention, fp32 SIMT.
// 256 threads; block handles 128 query rows of one (b,h).
// Per key-tile of 128: S = Q*K^T via 8x8 per-thread microtile, online softmax
// with shfl_xor row reductions over the 16 tx-lanes, P staged in padded smem,
// O += P@V via 8x4 per-thread microtile.
//
// Smem strides chosen for bank behavior:
//   Qs,Ks stride 65 (scalar loads conflict-free), Vs stride 68 (float4
//   conflict-free), Ps stride 132 (float4 STS 2-way, scalar LDS 2-way = floor).
// ---------------------------------------------------------------------------
#define QS_STRIDE 65
#define KS_STRIDE 65
#define VS_STRIDE 68
#define PS_STRIDE 132
#define ATTN_SMEM_FLOATS (128*QS_STRIDE + 128*KS_STRIDE + 128*VS_STRIDE + 128*PS_STRIDE + 128)

__global__ __launch_bounds__(256, 1) void attn_kernel(
    const float* __restrict__ Q,
    const float* __restrict__ Kt,
    const float* __restrict__ Vt,
    const int* __restrict__ mask,
    float* __restrict__ Out)
{
    extern __shared__ float sm[];
    float* Qs = sm;                        // [128][65]
    float* Ks = Qs + 128 * QS_STRIDE;      // [128][65]
    float* Vs = Ks + 128 * KS_STRIDE;      // [128][68]
    float* Ps = Vs + 128 * VS_STRIDE;      // [128][132]
    float* bsm = Ps + 128 * PS_STRIDE;     // [128]

    const int tid = threadIdx.x;
    const int tx = tid & 15;
    const int ty = tid >> 4;

    const int b = blockIdx.z, h = blockIdx.y;
    const int q0 = blockIdx.x * 128;

    const float* Qb = Q + (((size_t)(b * HH + h)) * SS + q0) * HD;
    const float* Kb = Kt + ((size_t)(b * HH + h)) * SS * HD;
    const float* Vb = Vt + ((size_t)(b * HH + h)) * SS * HD;
    const int* mb = mask + b * SS;

    // Load Q tile (128 x 64) once.
    for (int idx = tid; idx < 128 * 16; idx += 256) {
        int r = idx >> 4;
        int c4 = (idx & 15) * 4;
        float4 t = *(const float4*)(Qb + (size_t)r * HD + c4);
        float* d = Qs + r * QS_STRIDE + c4;
        d[0] = t.x; d[1] = t.y; d[2] = t.z; d[3] = t.w;
    }

    float Oacc[8][4];
#pragma unroll
    for (int i = 0; i < 8; i++)
#pragma unroll
        for (int c = 0; c < 4; c++) Oacc[i][c] = 0.f;
    float mrow[8], lrow[8];
#pragma unroll
    for (int i = 0; i < 8; i++) { mrow[i] = -1e30f; lrow[i] = 0.f; }

    for (int kt = 0; kt < SS; kt += 128) {
        __syncthreads();   // prior phase-2 consumers done with Ks/Vs/Ps
        // Load K (stride 65: 4 scalar stores) and V (stride 68: float4 store)
        for (int idx = tid; idx < 128 * 16; idx += 256) {
            int r = idx >> 4;
            int c4 = (idx & 15) * 4;
            float4 kv = *(const float4*)(Kb + (size_t)(kt + r) * HD + c4);
            float* dk = Ks + r * KS_STRIDE + c4;
            dk[0] = kv.x; dk[1] = kv.y; dk[2] = kv.z; dk[3] = kv.w;
            float4 vv = *(const float4*)(Vb + (size_t)(kt + r) * HD + c4);
            *(float4*)(Vs + r * VS_STRIDE + c4) = vv;
        }
        if (tid < 128)
            bsm[tid] = mb[kt + tid] ? 0.f : -1e9f;
        __syncthreads();

        // --- Phase 1: S = Q K^T microtile (8 rows x 8 keys per thread) ---
        float accS[8][8];
#pragma unroll
        for (int i = 0; i < 8; i++)
#pragma unroll
            for (int j = 0; j < 8; j++) accS[i][j] = 0.f;

#pragma unroll 4
        for (int d = 0; d < HD; d++) {
            float ar[8], br[8];
#pragma unroll
            for (int i = 0; i < 8; i++)
                ar[i] = Qs[(ty * 8 + i) * QS_STRIDE + d];
#pragma unroll
            for (int j = 0; j < 4; j++)
                br[j] = Ks[(tx * 4 + j) * KS_STRIDE + d];
#pragma unroll
            for (int j = 0; j < 4; j++)
                br[4 + j] = Ks[(64 + tx * 4 + j) * KS_STRIDE + d];
#pragma unroll
            for (int i = 0; i < 8; i++)
#pragma unroll
                for (int j = 0; j < 8; j++)
                    accS[i][j] += ar[i] * br[j];
        }

        // --- Online softmax per row (reduce across 16 tx lanes) ---
#pragma unroll
        for (int i = 0; i < 8; i++) {
            float s[8];
#pragma unroll
            for (int j = 0; j < 8; j++) {
                int key = (j < 4) ? (tx * 4 + j) : (64 + tx * 4 + (j - 4));
                s[j] = accS[i][j] * 0.125f + bsm[key];
            }
            float mx = s[0];
#pragma unroll
            for (int j = 1; j < 8; j++) mx = fmaxf(mx, s[j]);
#pragma unroll
            for (int off = 8; off >= 1; off >>= 1)
                mx = fmaxf(mx, __shfl_xor_sync(0xffffffffu, mx, off));
            float nm = fmaxf(mrow[i], mx);
            float corr = __expf(mrow[i] - nm);
            float ps = 0.f;
#pragma unroll
            for (int j = 0; j < 8; j++) {
                s[j] = __expf(s[j] - nm);
                ps += s[j];
            }
#pragma unroll
            for (int off = 8; off >= 1; off >>= 1)
                ps += __shfl_xor_sync(0xffffffffu, ps, off);
            lrow[i] = lrow[i] * corr + ps;
            mrow[i] = nm;
#pragma unroll
            for (int c = 0; c < 4; c++) Oacc[i][c] *= corr;
            // stage P to smem (transposed ownership resolved by layout [q][key])
            float* pr = Ps + (ty * 8 + i) * PS_STRIDE;
            float4 p0 = make_float4(s[0], s[1], s[2], s[3]);
            float4 p1 = make_float4(s[4], s[5], s[6], s[7]);
            *(float4*)(pr + tx * 4) = p0;
            *(float4*)(pr + 64 + tx * 4) = p1;
        }
        __syncthreads();

        // --- Phase 2: O += P @ V (8 rows x 4 cols per thread) ---
#pragma unroll 2
        for (int k = 0; k < 128; k++) {
            float pr[8];
#pragma unroll
            for (int i = 0; i < 8; i++)
                pr[i] = Ps[(ty * 8 + i) * PS_STRIDE + k];
            float4 vv = *(const float4*)(Vs + k * VS_STRIDE + tx * 4);
#pragma unroll
            for (int i = 0; i < 8; i++) {
                Oacc[i][0] += pr[i] * vv.x;
                Oacc[i][1] += pr[i] * vv.y;
                Oacc[i][2] += pr[i] * vv.z;
                Oacc[i][3] += pr[i] * vv.w;
            }
        }
    }

    // Final normalize + write (B,S,D) layout
#pragma unroll
    for (int i = 0; i < 8; i++) {
        int qg = q0 + ty * 8 + i;
        float inv = 1.0f / lrow[i];
        float4 o;
        o.x = Oacc[i][0] * inv;
        o.y = Oacc[i][1] * inv;
        o.z = Oacc[i][2] * inv;
        o.w = Oacc[i][3] * inv;
        *(float4*)(Out + ((size_t)(b * SS + qg)) * DD + h * HD + tx * 4) = o;
    }
}

// ---------------------------------------------------------------------------
extern "C" void kernel_launch(void* const* d_in, const int* in_sizes, int n_in,
                              void* d_out, int out_size)
{
    const float* xq = (const float*)d_in[0];
    const float* xk = (const float*)d_in[1];
    const float* xv = (const float*)d_in[2];
    const int*   mask = (const int*)d_in[3];
    const float* wq = (const float*)d_in[4];
    const float* bq = (const float*)d_in[5];
    const float* wk = (const float*)d_in[6];
    const float* bk = (const float*)d_in[7];
    const float* wv = (const float*)d_in[8];
    const float* bv = (const float*)d_in[9];
    const float* wo = (const float*)d_in[10];
    const float* bo = (const float*)d_in[11];
    float* out = (float*)d_out;

    float *Qp, *Kp, *Vp, *Ap;
    cudaGetSymbolAddress((void**)&Qp, g_Q);
    cudaGetSymbolAddress((void**)&Kp, g_K);
    cudaGetSymbolAddress((void**)&Vp, g_V);
    cudaGetSymbolAddress((void**)&Ap, g_A);

    static int attn_smem_set = 0;
    int attn_smem_bytes = ATTN_SMEM_FLOATS * 4;
    if (!attn_smem_set) {
        cudaFuncSetAttribute(attn_kernel,
                             cudaFuncAttributeMaxDynamicSharedMemorySize,
                             attn_smem_bytes);
        attn_smem_set = 1;
    }

    dim3 ggrid(DD / 128, MM / 128);   // (8, 32)
    sgemm_bias<<<ggrid, 256>>>(xq, wq, bq, Qp, 1);
    sgemm_bias<<<ggrid, 256>>>(xk, wk, bk, Kp, 1);
    sgemm_bias<<<ggrid, 256>>>(xv, wv, bv, Vp, 1);

    attn_kernel<<<dim3(SS / 128, HH, BB), 256, attn_smem_bytes>>>(Qp, Kp, Vp, mask, Ap);

    sgemm_bias<<<ggrid, 256>>>(Ap, wo, bo, out, 0);
}

// round 6
// speedup vs baseline: 1.5642x; 1.4458x over previous
#include <cuda_runtime.h>
#include <cuda_bf16.h>
#include <cstdint>

#define BB 2
#define SS 2048
#define DD 1024
#define HH 16
#define HD 64
#define MM (BB * SS)   // 4096 rows

// Scratch (allocation-free rule: __device__ globals)
__device__ __align__(16) float g_Q[BB * SS * DD];   // (B,H,S,HD)
__device__ __align__(16) float g_K[BB * SS * DD];   // (B,H,S,HD)
__device__ __align__(16) float g_V[BB * SS * DD];   // (B,H,S,HD)
__device__ __align__(16) float g_A[BB * SS * DD];   // attn out (B,S,D)

// ===========================================================================
// arch-portable tensor helpers (sm_80-era PTX: valid for compute_103)
// ===========================================================================
__device__ __forceinline__ uint32_t smem_u32(const void* p) {
    uint32_t a;
    asm("{ .reg .u64 t; cvta.to.shared.u64 t, %1; cvt.u32.u64 %0, t; }"
        : "=r"(a) : "l"(p));
    return a;
}

__device__ __forceinline__ void ldmatrix_x4(uint32_t& r0, uint32_t& r1,
                                            uint32_t& r2, uint32_t& r3,
                                            uint32_t addr) {
    asm volatile("ldmatrix.sync.aligned.m8n8.x4.shared.b16 {%0,%1,%2,%3}, [%4];"
                 : "=r"(r0), "=r"(r1), "=r"(r2), "=r"(r3) : "r"(addr));
}

__device__ __forceinline__ void mma_bf16(float& d0, float& d1, float& d2, float& d3,
                                         uint32_t a0, uint32_t a1, uint32_t a2, uint32_t a3,
                                         uint32_t b0, uint32_t b1) {
    asm volatile(
        "mma.sync.aligned.m16n8k16.row.col.f32.bf16.bf16.f32 "
        "{%0,%1,%2,%3}, {%4,%5,%6,%7}, {%8,%9}, {%0,%1,%2,%3};"
        : "+f"(d0), "+f"(d1), "+f"(d2), "+f"(d3)
        : "r"(a0), "r"(a1), "r"(a2), "r"(a3), "r"(b0), "r"(b1));
}

// pack two fp32 -> bf16x2 (x in low half), also return hi-parts as fp32
__device__ __forceinline__ uint32_t pack2(float x, float y) {
    __nv_bfloat162 h = __floats2bfloat162_rn(x, y);
    return *reinterpret_cast<uint32_t*>(&h);
}

// ===========================================================================
// bf16x3 mma.sync GEMM with bias: C[m,n] = sum_k A[m,k]*W[n,k] + bias[n]
// A:(4096,1024) rm, W:(1024,1024) rm. 128x128 tile/CTA, 256 thr, K-chunk 16.
// smem per buffer: Ahi/Alo/Bhi/Blo planes, each 128 rows x 48B (24 bf16).
// ===========================================================================
#define ASTR 24                         // bf16 elems per smem row (48 B)
#define PLANE_B (128 * ASTR * 2)        // bytes per plane = 6144
#define BUF_B   (4 * PLANE_B)           // 24576 per buffer
#define GEMM_SMEM (2 * BUF_B)           // 49152

__global__ __launch_bounds__(256, 1) void tc_gemm_bias(
    const float* __restrict__ A,
    const float* __restrict__ W,
    const float* __restrict__ bias,
    float* __restrict__ C,
    int head_split)
{
    extern __shared__ char smc[];
    const uint32_t sb = smem_u32(smc);

    const int tid = threadIdx.x;
    const int lane = tid & 31;
    const int wid = tid >> 5;
    const int warp_m = wid & 1;     // 2 x 64 rows
    const int warp_n = wid >> 1;    // 4 x 32 cols
    const int bm = blockIdx.y * 128;
    const int bn = blockIdx.x * 128;

    // gmem load slice: row r (0..127), cols c8..c8+7 of the 16-wide chunk
    const int r = tid >> 1;
    const int c8 = (tid & 1) * 8;
    const float* Ag = A + (size_t)(bm + r) * DD + c8;
    const float* Wg = W + (size_t)(bn + r) * DD + c8;
    // smem store offset (bytes) within a plane
    const uint32_t st_off = (uint32_t)(r * 48 + c8 * 2);

    // ldmatrix base addrs
    const int lrow = lane & 15;
    const int lbyte = (lane >> 4) * 16;
    const uint32_t a_ld0 = sb + (uint32_t)((warp_m * 64 + lrow) * 48 + lbyte);
    const uint32_t b_ld0 = sb + 2 * PLANE_B + (uint32_t)((warp_n * 32 + lrow) * 48 + lbyte);

    float acc[4][4][4];
#pragma unroll
    for (int i = 0; i < 4; i++)
#pragma unroll
        for (int j = 0; j < 4; j++)
#pragma unroll
            for (int k = 0; k < 4; k++) acc[i][j][k] = 0.f;

    float4 pa0, pa1, pb0, pb1;

    // ---- helpers as macros (keep everything in registers) ----
#define LOADCHUNK(cc)                                            \
    do {                                                         \
        const float* ap = Ag + (cc) * 16;                        \
        const float* wp = Wg + (cc) * 16;                        \
        pa0 = *(const float4*)(ap);                              \
        pa1 = *(const float4*)(ap + 4);                          \
        pb0 = *(const float4*)(wp);                              \
        pb1 = *(const float4*)(wp + 4);                          \
    } while (0)

#define CVTSTORE(bufo)                                                         \
    do {                                                                       \
        uint32_t h0 = pack2(pa0.x, pa0.y), h1 = pack2(pa0.z, pa0.w);           \
        uint32_t h2 = pack2(pa1.x, pa1.y), h3 = pack2(pa1.z, pa1.w);           \
        float4 hf0, hf1;                                                       \
        hf0.x = __uint_as_float(h0 << 16); hf0.y = __uint_as_float(h0 & 0xffff0000u); \
        hf0.z = __uint_as_float(h1 << 16); hf0.w = __uint_as_float(h1 & 0xffff0000u); \
        hf1.x = __uint_as_float(h2 << 16); hf1.y = __uint_as_float(h2 & 0xffff0000u); \
        hf1.z = __uint_as_float(h3 << 16); hf1.w = __uint_as_float(h3 & 0xffff0000u); \
        uint32_t l0 = pack2(pa0.x - hf0.x, pa0.y - hf0.y);                     \
        uint32_t l1 = pack2(pa0.z - hf0.z, pa0.w - hf0.w);                     \
        uint32_t l2 = pack2(pa1.x - hf1.x, pa1.y - hf1.y);                     \
        uint32_t l3 = pack2(pa1.z - hf1.z, pa1.w - hf1.w);                     \
        *(uint4*)(smc + (bufo) + st_off) = make_uint4(h0, h1, h2, h3);         \
        *(uint4*)(smc + (bufo) + PLANE_B + st_off) = make_uint4(l0, l1, l2, l3); \
        h0 = pack2(pb0.x, pb0.y); h1 = pack2(pb0.z, pb0.w);                    \
        h2 = pack2(pb1.x, pb1.y); h3 = pack2(pb1.z, pb1.w);                    \
        hf0.x = __uint_as_float(h0 << 16); hf0.y = __uint_as_float(h0 & 0xffff0000u); \
        hf0.z = __uint_as_float(h1 << 16); hf0.w = __uint_as_float(h1 & 0xffff0000u); \
        hf1.x = __uint_as_float(h2 << 16); hf1.y = __uint_as_float(h2 & 0xffff0000u); \
        hf1.z = __uint_as_float(h3 << 16); hf1.w = __uint_as_float(h3 & 0xffff0000u); \
        l0 = pack2(pb0.x - hf0.x, pb0.y - hf0.y);                              \
        l1 = pack2(pb0.z - hf0.z, pb0.w - hf0.w);                              \
        l2 = pack2(pb1.x - hf1.x, pb1.y - hf1.y);                              \
        l3 = pack2(pb1.z - hf1.z, pb1.w - hf1.w);                              \
        *(uint4*)(smc + (bufo) + 2 * PLANE_B + st_off) = make_uint4(h0, h1, h2, h3); \
        *(uint4*)(smc + (bufo) + 3 * PLANE_B + st_off) = make_uint4(l0, l1, l2, l3); \
    } while (0)

    // prologue: chunk 0
    LOADCHUNK(0);
    CVTSTORE(0);
    __syncthreads();

    for (int c = 0; c < 64; c++) {
        const uint32_t bufo = (uint32_t)(c & 1) * BUF_B;
        if (c < 63) LOADCHUNK(c + 1);

        // fragments
        uint32_t ah[4][4], al[4][4], bh[4][2], bl[4][2];
#pragma unroll
        for (int mi = 0; mi < 4; mi++) {
            ldmatrix_x4(ah[mi][0], ah[mi][1], ah[mi][2], ah[mi][3],
                        a_ld0 + bufo + mi * 768u);
            ldmatrix_x4(al[mi][0], al[mi][1], al[mi][2], al[mi][3],
                        a_ld0 + bufo + PLANE_B + mi * 768u);
        }
#pragma unroll
        for (int p = 0; p < 2; p++) {
            uint32_t t0, t1, t2, t3;
            ldmatrix_x4(t0, t1, t2, t3, b_ld0 + bufo + p * 768u);
            bh[p * 2][0] = t0;     bh[p * 2][1] = t2;
            bh[p * 2 + 1][0] = t1; bh[p * 2 + 1][1] = t3;
            ldmatrix_x4(t0, t1, t2, t3, b_ld0 + bufo + PLANE_B + p * 768u);
            bl[p * 2][0] = t0;     bl[p * 2][1] = t2;
            bl[p * 2 + 1][0] = t1; bl[p * 2 + 1][1] = t3;
        }

#pragma unroll
        for (int mi = 0; mi < 4; mi++)
#pragma unroll
            for (int ni = 0; ni < 4; ni++) {
                float* d = acc[mi][ni];
                mma_bf16(d[0], d[1], d[2], d[3],
                         ah[mi][0], ah[mi][1], ah[mi][2], ah[mi][3],
                         bh[ni][0], bh[ni][1]);
                mma_bf16(d[0], d[1], d[2], d[3],
                         ah[mi][0], ah[mi][1], ah[mi][2], ah[mi][3],
                         bl[ni][0], bl[ni][1]);
                mma_bf16(d[0], d[1], d[2], d[3],
                         al[mi][0], al[mi][1], al[mi][2], al[mi][3],
                         bh[ni][0], bh[ni][1]);
            }

        __syncthreads();
        if (c < 63) {
            CVTSTORE(((uint32_t)((c + 1) & 1)) * BUF_B);
            __syncthreads();
        }
    }

    // ---- epilogue: D fragment -> C with bias ----
#pragma unroll
    for (int mi = 0; mi < 4; mi++) {
#pragma unroll
        for (int ni = 0; ni < 4; ni++) {
            int m0 = bm + warp_m * 64 + mi * 16 + (lane >> 2);
            int n = bn + warp_n * 32 + ni * 8 + (lane & 3) * 2;
            float b0v = bias[n], b1v = bias[n + 1];
#pragma unroll
            for (int half = 0; half < 2; half++) {
                int m = m0 + half * 8;
                float2 v;
                v.x = acc[mi][ni][half * 2 + 0] + b0v;
                v.y = acc[mi][ni][half * 2 + 1] + b1v;
                if (head_split) {
                    int b = m >> 11;
                    int s = m & (SS - 1);
                    int h = n >> 6;
                    int hd = n & (HD - 1);
                    *(float2*)(C + (((size_t)(b * HH + h)) * SS + s) * HD + hd) = v;
                } else {
                    *(float2*)(C + (size_t)m * DD + n) = v;
                }
            }
        }
    }
#undef LOADCHUNK
#undef CVTSTORE
}

// ---------------------------------------------------------------------------
// Block-tiled flash attention, fp32 SIMT (unchanged from round 3)
// ---------------------------------------------------------------------------
#define QS_STRIDE 65
#define KS_STRIDE 65
#define VS_STRIDE 68
#define PS_STRIDE 132
#define ATTN_SMEM_FLOATS (128*QS_STRIDE + 128*KS_STRIDE + 128*VS_STRIDE + 128*PS_STRIDE + 128)

__global__ __launch_bounds__(256, 1) void attn_kernel(
    const float* __restrict__ Q,
    const float* __restrict__ Kt,
    const float* __restrict__ Vt,
    const int* __restrict__ mask,
    float* __restrict__ Out)
{
    extern __shared__ float sm[];
    float* Qs = sm;
    float* Ks = Qs + 128 * QS_STRIDE;
    float* Vs = Ks + 128 * KS_STRIDE;
    float* Ps = Vs + 128 * VS_STRIDE;
    float* bsm = Ps + 128 * PS_STRIDE;

    const int tid = threadIdx.x;
    const int tx = tid & 15;
    const int ty = tid >> 4;

    const int b = blockIdx.z, h = blockIdx.y;
    const int q0 = blockIdx.x * 128;

    const float* Qb = Q + (((size_t)(b * HH + h)) * SS + q0) * HD;
    const float* Kb = Kt + ((size_t)(b * HH + h)) * SS * HD;
    const float* Vb = Vt + ((size_t)(b * HH + h)) * SS * HD;
    const int* mb = mask + b * SS;

    for (int idx = tid; idx < 128 * 16; idx += 256) {
        int rr = idx >> 4;
        int c4 = (idx & 15) * 4;
        float4 t = *(const float4*)(Qb + (size_t)rr * HD + c4);
        float* d = Qs + rr * QS_STRIDE + c4;
        d[0] = t.x; d[1] = t.y; d[2] = t.z; d[3] = t.w;
    }

    float Oacc[8][4];
#pragma unroll
    for (int i = 0; i < 8; i++)
#pragma unroll
        for (int c = 0; c < 4; c++) Oacc[i][c] = 0.f;
    float mrow[8], lrow[8];
#pragma unroll
    for (int i = 0; i < 8; i++) { mrow[i] = -1e30f; lrow[i] = 0.f; }

    for (int kt = 0; kt < SS; kt += 128) {
        __syncthreads();
        for (int idx = tid; idx < 128 * 16; idx += 256) {
            int rr = idx >> 4;
            int c4 = (idx & 15) * 4;
            float4 kv = *(const float4*)(Kb + (size_t)(kt + rr) * HD + c4);
            float* dk = Ks + rr * KS_STRIDE + c4;
            dk[0] = kv.x; dk[1] = kv.y; dk[2] = kv.z; dk[3] = kv.w;
            float4 vv = *(const float4*)(Vb + (size_t)(kt + rr) * HD + c4);
            *(float4*)(Vs + rr * VS_STRIDE + c4) = vv;
        }
        if (tid < 128)
            bsm[tid] = mb[kt + tid] ? 0.f : -1e9f;
        __syncthreads();

        float accS[8][8];
#pragma unroll
        for (int i = 0; i < 8; i++)
#pragma unroll
            for (int j = 0; j < 8; j++) accS[i][j] = 0.f;

#pragma unroll 4
        for (int d = 0; d < HD; d++) {
            float ar[8], br[8];
#pragma unroll
            for (int i = 0; i < 8; i++)
                ar[i] = Qs[(ty * 8 + i) * QS_STRIDE + d];
#pragma unroll
            for (int j = 0; j < 4; j++)
                br[j] = Ks[(tx * 4 + j) * KS_STRIDE + d];
#pragma unroll
            for (int j = 0; j < 4; j++)
                br[4 + j] = Ks[(64 + tx * 4 + j) * KS_STRIDE + d];
#pragma unroll
            for (int i = 0; i < 8; i++)
#pragma unroll
                for (int j = 0; j < 8; j++)
                    accS[i][j] += ar[i] * br[j];
        }

#pragma unroll
        for (int i = 0; i < 8; i++) {
            float s[8];
#pragma unroll
            for (int j = 0; j < 8; j++) {
                int key = (j < 4) ? (tx * 4 + j) : (64 + tx * 4 + (j - 4));
                s[j] = accS[i][j] * 0.125f + bsm[key];
            }
            float mx = s[0];
#pragma unroll
            for (int j = 1; j < 8; j++) mx = fmaxf(mx, s[j]);
#pragma unroll
            for (int off = 8; off >= 1; off >>= 1)
                mx = fmaxf(mx, __shfl_xor_sync(0xffffffffu, mx, off));
            float nm = fmaxf(mrow[i], mx);
            float corr = __expf(mrow[i] - nm);
            float ps = 0.f;
#pragma unroll
            for (int j = 0; j < 8; j++) {
                s[j] = __expf(s[j] - nm);
                ps += s[j];
            }
#pragma unroll
            for (int off = 8; off >= 1; off >>= 1)
                ps += __shfl_xor_sync(0xffffffffu, ps, off);
            lrow[i] = lrow[i] * corr + ps;
            mrow[i] = nm;
#pragma unroll
            for (int c = 0; c < 4; c++) Oacc[i][c] *= corr;
            float* pr = Ps + (ty * 8 + i) * PS_STRIDE;
            float4 p0 = make_float4(s[0], s[1], s[2], s[3]);
            float4 p1 = make_float4(s[4], s[5], s[6], s[7]);
            *(float4*)(pr + tx * 4) = p0;
            *(float4*)(pr + 64 + tx * 4) = p1;
        }
        __syncthreads();

#pragma unroll 2
        for (int k = 0; k < 128; k++) {
            float pr[8];
#pragma unroll
            for (int i = 0; i < 8; i++)
                pr[i] = Ps[(ty * 8 + i) * PS_STRIDE + k];
            float4 vv = *(const float4*)(Vs + k * VS_STRIDE + tx * 4);
#pragma unroll
            for (int i = 0; i < 8; i++) {
                Oacc[i][0] += pr[i] * vv.x;
                Oacc[i][1] += pr[i] * vv.y;
                Oacc[i][2] += pr[i] * vv.z;
                Oacc[i][3] += pr[i] * vv.w;
            }
        }
    }

#pragma unroll
    for (int i = 0; i < 8; i++) {
        int qg = q0 + ty * 8 + i;
        float inv = 1.0f / lrow[i];
        float4 o;
        o.x = Oacc[i][0] * inv;
        o.y = Oacc[i][1] * inv;
        o.z = Oacc[i][2] * inv;
        o.w = Oacc[i][3] * inv;
        *(float4*)(Out + ((size_t)(b * SS + qg)) * DD + h * HD + tx * 4) = o;
    }
}

// ---------------------------------------------------------------------------
extern "C" void kernel_launch(void* const* d_in, const int* in_sizes, int n_in,
                              void* d_out, int out_size)
{
    const float* xq = (const float*)d_in[0];
    const float* xk = (const float*)d_in[1];
    const float* xv = (const float*)d_in[2];
    const int*   mask = (const int*)d_in[3];
    const float* wq = (const float*)d_in[4];
    const float* bq = (const float*)d_in[5];
    const float* wk = (const float*)d_in[6];
    const float* bk = (const float*)d_in[7];
    const float* wv = (const float*)d_in[8];
    const float* bv = (const float*)d_in[9];
    const float* wo = (const float*)d_in[10];
    const float* bo = (const float*)d_in[11];
    float* out = (float*)d_out;

    float *Qp, *Kp, *Vp, *Ap;
    cudaGetSymbolAddress((void**)&Qp, g_Q);
    cudaGetSymbolAddress((void**)&Kp, g_K);
    cudaGetSymbolAddress((void**)&Vp, g_V);
    cudaGetSymbolAddress((void**)&Ap, g_A);

    int attn_smem_bytes = ATTN_SMEM_FLOATS * 4;
    cudaFuncSetAttribute(attn_kernel,
                         cudaFuncAttributeMaxDynamicSharedMemorySize,
                         attn_smem_bytes);
    cudaFuncSetAttribute(tc_gemm_bias,
                         cudaFuncAttributeMaxDynamicSharedMemorySize,
                         GEMM_SMEM);

    dim3 ggrid(DD / 128, MM / 128);   // (8, 32)
    tc_gemm_bias<<<ggrid, 256, GEMM_SMEM>>>(xq, wq, bq, Qp, 1);
    tc_gemm_bias<<<ggrid, 256, GEMM_SMEM>>>(xk, wk, bk, Kp, 1);
    tc_gemm_bias<<<ggrid, 256, GEMM_SMEM>>>(xv, wv, bv, Vp, 1);

    attn_kernel<<<dim3(SS / 128, HH, BB), 256, attn_smem_bytes>>>(Qp, Kp, Vp, mask, Ap);

    tc_gemm_bias<<<ggrid, 256, GEMM_SMEM>>>(Ap, wo, bo, out, 0);
}

// round 7
// speedup vs baseline: 2.3732x; 1.5172x over previous
#include <cuda_runtime.h>
#include <cuda_bf16.h>
#include <cstdint>

#define BB 2
#define SS 2048
#define DD 1024
#define HH 16
#define HD 64
#define MM (BB * SS)   // 4096 rows

// Scratch (allocation-free rule: __device__ globals)
__device__ __align__(16) float g_Q[BB * SS * DD];    // (B,H,S,HD)
__device__ __align__(16) float g_K[BB * SS * DD];    // (B,H,S,HD)
__device__ __align__(16) float g_V[BB * SS * DD];    // (B,H,S,HD)
__device__ __align__(16) float g_Kc[BB * SS * DD];   // compacted K
__device__ __align__(16) float g_Vc[BB * SS * DD];   // compacted V
__device__ __align__(16) float g_A[BB * SS * DD];    // attn out (B,S,D)
__device__ int g_idx[BB * SS];
__device__ int g_cnt[BB];

// ===========================================================================
// arch-portable tensor helpers (sm_80-era PTX: valid for compute_103)
// ===========================================================================
__device__ __forceinline__ uint32_t smem_u32(const void* p) {
    uint32_t a;
    asm("{ .reg .u64 t; cvta.to.shared.u64 t, %1; cvt.u32.u64 %0, t; }"
        : "=r"(a) : "l"(p));
    return a;
}

__device__ __forceinline__ void ldmatrix_x4(uint32_t& r0, uint32_t& r1,
                                            uint32_t& r2, uint32_t& r3,
                                            uint32_t addr) {
    asm volatile("ldmatrix.sync.aligned.m8n8.x4.shared.b16 {%0,%1,%2,%3}, [%4];"
                 : "=r"(r0), "=r"(r1), "=r"(r2), "=r"(r3) : "r"(addr));
}

__device__ __forceinline__ void mma_bf16(float& d0, float& d1, float& d2, float& d3,
                                         uint32_t a0, uint32_t a1, uint32_t a2, uint32_t a3,
                                         uint32_t b0, uint32_t b1) {
    asm volatile(
        "mma.sync.aligned.m16n8k16.row.col.f32.bf16.bf16.f32 "
        "{%0,%1,%2,%3}, {%4,%5,%6,%7}, {%8,%9}, {%0,%1,%2,%3};"
        : "+f"(d0), "+f"(d1), "+f"(d2), "+f"(d3)
        : "r"(a0), "r"(a1), "r"(a2), "r"(a3), "r"(b0), "r"(b1));
}

__device__ __forceinline__ uint32_t pack2(float x, float y) {
    __nv_bfloat162 h = __floats2bfloat162_rn(x, y);
    return *reinterpret_cast<uint32_t*>(&h);
}

// ===========================================================================
// bf16x3 mma.sync GEMM with bias (unchanged from round 6)
// ===========================================================================
#define ASTR 24
#define PLANE_B (128 * ASTR * 2)
#define BUF_B   (4 * PLANE_B)
#define GEMM_SMEM (2 * BUF_B)

__global__ __launch_bounds__(256, 1) void tc_gemm_bias(
    const float* __restrict__ A,
    const float* __restrict__ W,
    const float* __restrict__ bias,
    float* __restrict__ C,
    int head_split)
{
    extern __shared__ char smc[];
    const uint32_t sb = smem_u32(smc);

    const int tid = threadIdx.x;
    const int lane = tid & 31;
    const int wid = tid >> 5;
    const int warp_m = wid & 1;
    const int warp_n = wid >> 1;
    const int bm = blockIdx.y * 128;
    const int bn = blockIdx.x * 128;

    const int r = tid >> 1;
    const int c8 = (tid & 1) * 8;
    const float* Ag = A + (size_t)(bm + r) * DD + c8;
    const float* Wg = W + (size_t)(bn + r) * DD + c8;
    const uint32_t st_off = (uint32_t)(r * 48 + c8 * 2);

    const int lrow = lane & 15;
    const int lbyte = (lane >> 4) * 16;
    const uint32_t a_ld0 = sb + (uint32_t)((warp_m * 64 + lrow) * 48 + lbyte);
    const uint32_t b_ld0 = sb + 2 * PLANE_B + (uint32_t)((warp_n * 32 + lrow) * 48 + lbyte);

    float acc[4][4][4];
#pragma unroll
    for (int i = 0; i < 4; i++)
#pragma unroll
        for (int j = 0; j < 4; j++)
#pragma unroll
            for (int k = 0; k < 4; k++) acc[i][j][k] = 0.f;

    float4 pa0, pa1, pb0, pb1;

#define LOADCHUNK(cc)                                            \
    do {                                                         \
        const float* ap = Ag + (cc) * 16;                        \
        const float* wp = Wg + (cc) * 16;                        \
        pa0 = *(const float4*)(ap);                              \
        pa1 = *(const float4*)(ap + 4);                          \
        pb0 = *(const float4*)(wp);                              \
        pb1 = *(const float4*)(wp + 4);                          \
    } while (0)

#define CVTSTORE(bufo)                                                         \
    do {                                                                       \
        uint32_t h0 = pack2(pa0.x, pa0.y), h1 = pack2(pa0.z, pa0.w);           \
        uint32_t h2 = pack2(pa1.x, pa1.y), h3 = pack2(pa1.z, pa1.w);           \
        float4 hf0, hf1;                                                       \
        hf0.x = __uint_as_float(h0 << 16); hf0.y = __uint_as_float(h0 & 0xffff0000u); \
        hf0.z = __uint_as_float(h1 << 16); hf0.w = __uint_as_float(h1 & 0xffff0000u); \
        hf1.x = __uint_as_float(h2 << 16); hf1.y = __uint_as_float(h2 & 0xffff0000u); \
        hf1.z = __uint_as_float(h3 << 16); hf1.w = __uint_as_float(h3 & 0xffff0000u); \
        uint32_t l0 = pack2(pa0.x - hf0.x, pa0.y - hf0.y);                     \
        uint32_t l1 = pack2(pa0.z - hf0.z, pa0.w - hf0.w);                     \
        uint32_t l2 = pack2(pa1.x - hf1.x, pa1.y - hf1.y);                     \
        uint32_t l3 = pack2(pa1.z - hf1.z, pa1.w - hf1.w);                     \
        *(uint4*)(smc + (bufo) + st_off) = make_uint4(h0, h1, h2, h3);         \
        *(uint4*)(smc + (bufo) + PLANE_B + st_off) = make_uint4(l0, l1, l2, l3); \
        h0 = pack2(pb0.x, pb0.y); h1 = pack2(pb0.z, pb0.w);                    \
        h2 = pack2(pb1.x, pb1.y); h3 = pack2(pb1.z, pb1.w);                    \
        hf0.x = __uint_as_float(h0 << 16); hf0.y = __uint_as_float(h0 & 0xffff0000u); \
        hf0.z = __uint_as_float(h1 << 16); hf0.w = __uint_as_float(h1 & 0xffff0000u); \
        hf1.x = __uint_as_float(h2 << 16); hf1.y = __uint_as_float(h2 & 0xffff0000u); \
        hf1.z = __uint_as_float(h3 << 16); hf1.w = __uint_as_float(h3 & 0xffff0000u); \
        l0 = pack2(pb0.x - hf0.x, pb0.y - hf0.y);                              \
        l1 = pack2(pb0.z - hf0.z, pb0.w - hf0.w);                              \
        l2 = pack2(pb1.x - hf1.x, pb1.y - hf1.y);                              \
        l3 = pack2(pb1.z - hf1.z, pb1.w - hf1.w);                              \
        *(uint4*)(smc + (bufo) + 2 * PLANE_B + st_off) = make_uint4(h0, h1, h2, h3); \
        *(uint4*)(smc + (bufo) + 3 * PLANE_B + st_off) = make_uint4(l0, l1, l2, l3); \
    } while (0)

    LOADCHUNK(0);
    CVTSTORE(0);
    __syncthreads();

    for (int c = 0; c < 64; c++) {
        const uint32_t bufo = (uint32_t)(c & 1) * BUF_B;
        if (c < 63) LOADCHUNK(c + 1);

        uint32_t ah[4][4], al[4][4], bh[4][2], bl[4][2];
#pragma unroll
        for (int mi = 0; mi < 4; mi++) {
            ldmatrix_x4(ah[mi][0], ah[mi][1], ah[mi][2], ah[mi][3],
                        a_ld0 + bufo + mi * 768u);
            ldmatrix_x4(al[mi][0], al[mi][1], al[mi][2], al[mi][3],
                        a_ld0 + bufo + PLANE_B + mi * 768u);
        }
#pragma unroll
        for (int p = 0; p < 2; p++) {
            uint32_t t0, t1, t2, t3;
            ldmatrix_x4(t0, t1, t2, t3, b_ld0 + bufo + p * 768u);
            bh[p * 2][0] = t0;     bh[p * 2][1] = t2;
            bh[p * 2 + 1][0] = t1; bh[p * 2 + 1][1] = t3;
            ldmatrix_x4(t0, t1, t2, t3, b_ld0 + bufo + PLANE_B + p * 768u);
            bl[p * 2][0] = t0;     bl[p * 2][1] = t2;
            bl[p * 2 + 1][0] = t1; bl[p * 2 + 1][1] = t3;
        }

#pragma unroll
        for (int mi = 0; mi < 4; mi++)
#pragma unroll
            for (int ni = 0; ni < 4; ni++) {
                float* d = acc[mi][ni];
                mma_bf16(d[0], d[1], d[2], d[3],
                         ah[mi][0], ah[mi][1], ah[mi][2], ah[mi][3],
                         bh[ni][0], bh[ni][1]);
                mma_bf16(d[0], d[1], d[2], d[3],
                         ah[mi][0], ah[mi][1], ah[mi][2], ah[mi][3],
                         bl[ni][0], bl[ni][1]);
                mma_bf16(d[0], d[1], d[2], d[3],
                         al[mi][0], al[mi][1], al[mi][2], al[mi][3],
                         bh[ni][0], bh[ni][1]);
            }

        __syncthreads();
        if (c < 63) {
            CVTSTORE(((uint32_t)((c + 1) & 1)) * BUF_B);
            __syncthreads();
        }
    }

#pragma unroll
    for (int mi = 0; mi < 4; mi++) {
#pragma unroll
        for (int ni = 0; ni < 4; ni++) {
            int m0 = bm + warp_m * 64 + mi * 16 + (lane >> 2);
            int n = bn + warp_n * 32 + ni * 8 + (lane & 3) * 2;
            float b0v = bias[n], b1v = bias[n + 1];
#pragma unroll
            for (int half = 0; half < 2; half++) {
                int m = m0 + half * 8;
                float2 v;
                v.x = acc[mi][ni][half * 2 + 0] + b0v;
                v.y = acc[mi][ni][half * 2 + 1] + b1v;
                if (head_split) {
                    int b = m >> 11;
                    int s = m & (SS - 1);
                    int h = n >> 6;
                    int hd = n & (HD - 1);
                    *(float2*)(C + (((size_t)(b * HH + h)) * SS + s) * HD + hd) = v;
                } else {
                    *(float2*)(C + (size_t)m * DD + n) = v;
                }
            }
        }
    }
#undef LOADCHUNK
#undef CVTSTORE
}

// ===========================================================================
// Mask compaction: per batch, build list of live key indices + count.
// 1 block / batch, 1024 threads, each handles 2 mask entries.
// ===========================================================================
__global__ __launch_bounds__(1024) void compact_idx(
    const int* __restrict__ mask, int* __restrict__ idx, int* __restrict__ cnt)
{
    const int b = blockIdx.x;
    __shared__ int wsum[32];
    const int t = threadIdx.x;
    const int lane = t & 31;
    const int w = t >> 5;

    const int p0 = 2 * t, p1 = 2 * t + 1;
    const int m0 = mask[b * SS + p0] != 0;
    const int m1 = mask[b * SS + p1] != 0;
    const int local = m0 + m1;

    int v = local;
#pragma unroll
    for (int off = 1; off < 32; off <<= 1) {
        int u = __shfl_up_sync(0xffffffffu, v, off);
        if (lane >= off) v += u;
    }
    if (lane == 31) wsum[w] = v;
    __syncthreads();
    if (w == 0) {
        int s = wsum[lane];
#pragma unroll
        for (int off = 1; off < 32; off <<= 1) {
            int u = __shfl_up_sync(0xffffffffu, s, off);
            if (lane >= off) s += u;
        }
        wsum[lane] = s;
    }
    __syncthreads();

    const int base = (w > 0 ? wsum[w - 1] : 0) + (v - local);
    if (m0) idx[b * SS + base] = p0;
    if (m1) idx[b * SS + base + m0] = p1;
    if (t == 1023) cnt[b] = wsum[31];
}

// ===========================================================================
// Gather live K/V rows into compacted arrays; zero-pad to 128 multiple.
// grid (SS/128, HH, BB), 256 threads.
// ===========================================================================
__global__ __launch_bounds__(256) void gather_kv(
    const float* __restrict__ K, const float* __restrict__ V,
    const int* __restrict__ idx, const int* __restrict__ cnt,
    float* __restrict__ Kc, float* __restrict__ Vc)
{
    const int b = blockIdx.z, h = blockIdx.y;
    const int j0 = blockIdx.x * 128;
    const int nlive = cnt[b];
    const int npad = (nlive + 127) & ~127;
    if (j0 >= npad) return;

    const size_t bh = (size_t)(b * HH + h) * SS;
    const int* ib = idx + b * SS;

    for (int t = threadIdx.x; t < 128 * 16; t += 256) {
        int j = j0 + (t >> 4);
        int c4 = (t & 15) * 4;
        float4 kv, vv;
        if (j < nlive) {
            int src = ib[j];
            kv = *(const float4*)(K + (bh + src) * HD + c4);
            vv = *(const float4*)(V + (bh + src) * HD + c4);
        } else {
            kv = make_float4(0.f, 0.f, 0.f, 0.f);
            vv = kv;
        }
        *(float4*)(Kc + (bh + j) * HD + c4) = kv;
        *(float4*)(Vc + (bh + j) * HD + c4) = vv;
    }
}

// ---------------------------------------------------------------------------
// Block-tiled flash attention over COMPACTED keys (loop bound = cnt[b]).
// ---------------------------------------------------------------------------
#define QS_STRIDE 65
#define KS_STRIDE 65
#define VS_STRIDE 68
#define PS_STRIDE 132
#define ATTN_SMEM_FLOATS (128*QS_STRIDE + 128*KS_STRIDE + 128*VS_STRIDE + 128*PS_STRIDE + 128)

__global__ __launch_bounds__(256, 1) void attn_kernel(
    const float* __restrict__ Q,
    const float* __restrict__ Kt,
    const float* __restrict__ Vt,
    const int* __restrict__ cnt,
    float* __restrict__ Out)
{
    extern __shared__ float sm[];
    float* Qs = sm;
    float* Ks = Qs + 128 * QS_STRIDE;
    float* Vs = Ks + 128 * KS_STRIDE;
    float* Ps = Vs + 128 * VS_STRIDE;
    float* bsm = Ps + 128 * PS_STRIDE;

    const int tid = threadIdx.x;
    const int tx = tid & 15;
    const int ty = tid >> 4;

    const int b = blockIdx.z, h = blockIdx.y;
    const int q0 = blockIdx.x * 128;
    const int nlive = cnt[b];

    const float* Qb = Q + (((size_t)(b * HH + h)) * SS + q0) * HD;
    const float* Kb = Kt + ((size_t)(b * HH + h)) * SS * HD;
    const float* Vb = Vt + ((size_t)(b * HH + h)) * SS * HD;

    for (int idx = tid; idx < 128 * 16; idx += 256) {
        int rr = idx >> 4;
        int c4 = (idx & 15) * 4;
        float4 t = *(const float4*)(Qb + (size_t)rr * HD + c4);
        float* d = Qs + rr * QS_STRIDE + c4;
        d[0] = t.x; d[1] = t.y; d[2] = t.z; d[3] = t.w;
    }

    float Oacc[8][4];
#pragma unroll
    for (int i = 0; i < 8; i++)
#pragma unroll
        for (int c = 0; c < 4; c++) Oacc[i][c] = 0.f;
    float mrow[8], lrow[8];
#pragma unroll
    for (int i = 0; i < 8; i++) { mrow[i] = -1e30f; lrow[i] = 0.f; }

    for (int kt = 0; kt < nlive; kt += 128) {
        __syncthreads();
        for (int idx = tid; idx < 128 * 16; idx += 256) {
            int rr = idx >> 4;
            int c4 = (idx & 15) * 4;
            float4 kv = *(const float4*)(Kb + (size_t)(kt + rr) * HD + c4);
            float* dk = Ks + rr * KS_STRIDE + c4;
            dk[0] = kv.x; dk[1] = kv.y; dk[2] = kv.z; dk[3] = kv.w;
            float4 vv = *(const float4*)(Vb + (size_t)(kt + rr) * HD + c4);
            *(float4*)(Vs + rr * VS_STRIDE + c4) = vv;
        }
        if (tid < 128)
            bsm[tid] = (kt + tid < nlive) ? 0.f : -1e9f;
        __syncthreads();

        float accS[8][8];
#pragma unroll
        for (int i = 0; i < 8; i++)
#pragma unroll
            for (int j = 0; j < 8; j++) accS[i][j] = 0.f;

#pragma unroll 4
        for (int d = 0; d < HD; d++) {
            float ar[8], br[8];
#pragma unroll
            for (int i = 0; i < 8; i++)
                ar[i] = Qs[(ty * 8 + i) * QS_STRIDE + d];
#pragma unroll
            for (int j = 0; j < 4; j++)
                br[j] = Ks[(tx * 4 + j) * KS_STRIDE + d];
#pragma unroll
            for (int j = 0; j < 4; j++)
                br[4 + j] = Ks[(64 + tx * 4 + j) * KS_STRIDE + d];
#pragma unroll
            for (int i = 0; i < 8; i++)
#pragma unroll
                for (int j = 0; j < 8; j++)
                    accS[i][j] += ar[i] * br[j];
        }

#pragma unroll
        for (int i = 0; i < 8; i++) {
            float s[8];
#pragma unroll
            for (int j = 0; j < 8; j++) {
                int key = (j < 4) ? (tx * 4 + j) : (64 + tx * 4 + (j - 4));
                s[j] = accS[i][j] * 0.125f + bsm[key];
            }
            float mx = s[0];
#pragma unroll
            for (int j = 1; j < 8; j++) mx = fmaxf(mx, s[j]);
#pragma unroll
            for (int off = 8; off >= 1; off >>= 1)
                mx = fmaxf(mx, __shfl_xor_sync(0xffffffffu, mx, off));
            float nm = fmaxf(mrow[i], mx);
            float corr = __expf(mrow[i] - nm);
            float ps = 0.f;
#pragma unroll
            for (int j = 0; j < 8; j++) {
                s[j] = __expf(s[j] - nm);
                ps += s[j];
            }
#pragma unroll
            for (int off = 8; off >= 1; off >>= 1)
                ps += __shfl_xor_sync(0xffffffffu, ps, off);
            lrow[i] = lrow[i] * corr + ps;
            mrow[i] = nm;
#pragma unroll
            for (int c = 0; c < 4; c++) Oacc[i][c] *= corr;
            float* pr = Ps + (ty * 8 + i) * PS_STRIDE;
            float4 p0 = make_float4(s[0], s[1], s[2], s[3]);
            float4 p1 = make_float4(s[4], s[5], s[6], s[7]);
            *(float4*)(pr + tx * 4) = p0;
            *(float4*)(pr + 64 + tx * 4) = p1;
        }
        __syncthreads();

#pragma unroll 2
        for (int k = 0; k < 128; k++) {
            float pr[8];
#pragma unroll
            for (int i = 0; i < 8; i++)
                pr[i] = Ps[(ty * 8 + i) * PS_STRIDE + k];
            float4 vv = *(const float4*)(Vs + k * VS_STRIDE + tx * 4);
#pragma unroll
            for (int i = 0; i < 8; i++) {
                Oacc[i][0] += pr[i] * vv.x;
                Oacc[i][1] += pr[i] * vv.y;
                Oacc[i][2] += pr[i] * vv.z;
                Oacc[i][3] += pr[i] * vv.w;
            }
        }
    }

#pragma unroll
    for (int i = 0; i < 8; i++) {
        int qg = q0 + ty * 8 + i;
        float inv = 1.0f / lrow[i];
        float4 o;
        o.x = Oacc[i][0] * inv;
        o.y = Oacc[i][1] * inv;
        o.z = Oacc[i][2] * inv;
        o.w = Oacc[i][3] * inv;
        *(float4*)(Out + ((size_t)(b * SS + qg)) * DD + h * HD + tx * 4) = o;
    }
}

// ---------------------------------------------------------------------------
extern "C" void kernel_launch(void* const* d_in, const int* in_sizes, int n_in,
                              void* d_out, int out_size)
{
    const float* xq = (const float*)d_in[0];
    const float* xk = (const float*)d_in[1];
    const float* xv = (const float*)d_in[2];
    const int*   mask = (const int*)d_in[3];
    const float* wq = (const float*)d_in[4];
    const float* bq = (const float*)d_in[5];
    const float* wk = (const float*)d_in[6];
    const float* bk = (const float*)d_in[7];
    const float* wv = (const float*)d_in[8];
    const float* bv = (const float*)d_in[9];
    const float* wo = (const float*)d_in[10];
    const float* bo = (const float*)d_in[11];
    float* out = (float*)d_out;

    float *Qp, *Kp, *Vp, *Kcp, *Vcp, *Ap;
    int *idxp, *cntp;
    cudaGetSymbolAddress((void**)&Qp, g_Q);
    cudaGetSymbolAddress((void**)&Kp, g_K);
    cudaGetSymbolAddress((void**)&Vp, g_V);
    cudaGetSymbolAddress((void**)&Kcp, g_Kc);
    cudaGetSymbolAddress((void**)&Vcp, g_Vc);
    cudaGetSymbolAddress((void**)&Ap, g_A);
    cudaGetSymbolAddress((void**)&idxp, g_idx);
    cudaGetSymbolAddress((void**)&cntp, g_cnt);

    int attn_smem_bytes = ATTN_SMEM_FLOATS * 4;
    cudaFuncSetAttribute(attn_kernel,
                         cudaFuncAttributeMaxDynamicSharedMemorySize,
                         attn_smem_bytes);
    cudaFuncSetAttribute(tc_gemm_bias,
                         cudaFuncAttributeMaxDynamicSharedMemorySize,
                         GEMM_SMEM);

    dim3 ggrid(DD / 128, MM / 128);   // (8, 32)
    tc_gemm_bias<<<ggrid, 256, GEMM_SMEM>>>(xq, wq, bq, Qp, 1);
    tc_gemm_bias<<<ggrid, 256, GEMM_SMEM>>>(xk, wk, bk, Kp, 1);
    tc_gemm_bias<<<ggrid, 256, GEMM_SMEM>>>(xv, wv, bv, Vp, 1);

    compact_idx<<<BB, 1024>>>(mask, idxp, cntp);
    gather_kv<<<dim3(SS / 128, HH, BB), 256>>>(Kp, Vp, idxp, cntp, Kcp, Vcp);

    attn_kernel<<<dim3(SS / 128, HH, BB), 256, attn_smem_bytes>>>(Qp, Kcp, Vcp, cntp, Ap);

    tc_gemm_bias<<<ggrid, 256, GEMM_SMEM>>>(Ap, wo, bo, out, 0);
}

// round 9
// speedup vs baseline: 3.8130x; 1.6067x over previous
#include <cuda_runtime.h>
#include <cuda_bf16.h>
#include <cstdint>

#define BB 2
#define SS 2048
#define DD 1024
#define HH 16
#define HD 64
#define MM (BB * SS)   // 4096 rows

// Scratch (allocation-free rule: __device__ globals)
__device__ __align__(16) float g_Q[BB * SS * DD];    // (B,H,S,HD) fp32
__device__ __align__(16) float g_K[BB * SS * DD];    // (B,H,S,HD) fp32
__device__ __align__(16) float g_V[BB * SS * DD];    // (B,H,S,HD) fp32
__device__ __align__(16) __nv_bfloat16 g_Kh[BB * SS * DD];  // compacted K hi
__device__ __align__(16) __nv_bfloat16 g_Kl[BB * SS * DD];  // compacted K lo
__device__ __align__(16) __nv_bfloat16 g_Vh[BB * SS * DD];  // compacted V hi
__device__ __align__(16) __nv_bfloat16 g_Vl[BB * SS * DD];  // compacted V lo
__device__ __align__(16) float g_A[BB * SS * DD];    // attn out (B,S,D)
__device__ int g_idx[BB * SS];
__device__ int g_cnt[BB];

// ===========================================================================
// arch-portable tensor helpers
// ===========================================================================
__device__ __forceinline__ uint32_t smem_u32(const void* p) {
    uint32_t a;
    asm("{ .reg .u64 t; cvta.to.shared.u64 t, %1; cvt.u32.u64 %0, t; }"
        : "=r"(a) : "l"(p));
    return a;
}

__device__ __forceinline__ void ldmatrix_x4(uint32_t& r0, uint32_t& r1,
                                            uint32_t& r2, uint32_t& r3,
                                            uint32_t addr) {
    asm volatile("ldmatrix.sync.aligned.m8n8.x4.shared.b16 {%0,%1,%2,%3}, [%4];"
                 : "=r"(r0), "=r"(r1), "=r"(r2), "=r"(r3) : "r"(addr));
}

__device__ __forceinline__ void ldmatrix_x4_trans(uint32_t& r0, uint32_t& r1,
                                                  uint32_t& r2, uint32_t& r3,
                                                  uint32_t addr) {
    asm volatile("ldmatrix.sync.aligned.m8n8.x4.trans.shared.b16 {%0,%1,%2,%3}, [%4];"
                 : "=r"(r0), "=r"(r1), "=r"(r2), "=r"(r3) : "r"(addr));
}

__device__ __forceinline__ void mma_bf16(float* d,
                                         uint32_t a0, uint32_t a1, uint32_t a2, uint32_t a3,
                                         uint32_t b0, uint32_t b1) {
    asm volatile(
        "mma.sync.aligned.m16n8k16.row.col.f32.bf16.bf16.f32 "
        "{%0,%1,%2,%3}, {%4,%5,%6,%7}, {%8,%9}, {%0,%1,%2,%3};"
        : "+f"(d[0]), "+f"(d[1]), "+f"(d[2]), "+f"(d[3])
        : "r"(a0), "r"(a1), "r"(a2), "r"(a3), "r"(b0), "r"(b1));
}

__device__ __forceinline__ uint32_t pack2(float x, float y) {
    __nv_bfloat162 h = __floats2bfloat162_rn(x, y);
    return *reinterpret_cast<uint32_t*>(&h);
}

// split 4 floats into bf16 hi pair-regs and lo pair-regs
__device__ __forceinline__ void split4(float x, float y, float z, float w,
                                       uint32_t& h0, uint32_t& h1,
                                       uint32_t& l0, uint32_t& l1) {
    h0 = pack2(x, y); h1 = pack2(z, w);
    float fx = __uint_as_float(h0 << 16), fy = __uint_as_float(h0 & 0xffff0000u);
    float fz = __uint_as_float(h1 << 16), fw = __uint_as_float(h1 & 0xffff0000u);
    l0 = pack2(x - fx, y - fy); l1 = pack2(z - fz, w - fw);
}

#define SW128(o) ((o) ^ (((o) >> 3) & 0x70))

// ===========================================================================
// bf16x3 mma.sync GEMM with bias (unchanged from round 6)
// ===========================================================================
#define ASTR 24
#define PLANE_B (128 * ASTR * 2)
#define BUF_B   (4 * PLANE_B)
#define GEMM_SMEM (2 * BUF_B)

__global__ __launch_bounds__(256, 1) void tc_gemm_bias(
    const float* __restrict__ A,
    const float* __restrict__ W,
    const float* __restrict__ bias,
    float* __restrict__ C,
    int head_split)
{
    extern __shared__ char smc[];
    const uint32_t sb = smem_u32(smc);

    const int tid = threadIdx.x;
    const int lane = tid & 31;
    const int wid = tid >> 5;
    const int warp_m = wid & 1;
    const int warp_n = wid >> 1;
    const int bm = blockIdx.y * 128;
    const int bn = blockIdx.x * 128;

    const int r = tid >> 1;
    const int c8 = (tid & 1) * 8;
    const float* Ag = A + (size_t)(bm + r) * DD + c8;
    const float* Wg = W + (size_t)(bn + r) * DD + c8;
    const uint32_t st_off = (uint32_t)(r * 48 + c8 * 2);

    const int lrow = lane & 15;
    const int lbyte = (lane >> 4) * 16;
    const uint32_t a_ld0 = sb + (uint32_t)((warp_m * 64 + lrow) * 48 + lbyte);
    const uint32_t b_ld0 = sb + 2 * PLANE_B + (uint32_t)((warp_n * 32 + lrow) * 48 + lbyte);

    float acc[4][4][4];
#pragma unroll
    for (int i = 0; i < 4; i++)
#pragma unroll
        for (int j = 0; j < 4; j++)
#pragma unroll
            for (int k = 0; k < 4; k++) acc[i][j][k] = 0.f;

    float4 pa0, pa1, pb0, pb1;

#define LOADCHUNK(cc)                                            \
    do {                                                         \
        const float* ap = Ag + (cc) * 16;                        \
        const float* wp = Wg + (cc) * 16;                        \
        pa0 = *(const float4*)(ap);                              \
        pa1 = *(const float4*)(ap + 4);                          \
        pb0 = *(const float4*)(wp);                              \
        pb1 = *(const float4*)(wp + 4);                          \
    } while (0)

#define CVTSTORE(bufo)                                                         \
    do {                                                                       \
        uint32_t h0, h1, h2, h3, l0, l1, l2, l3;                               \
        split4(pa0.x, pa0.y, pa0.z, pa0.w, h0, h1, l0, l1);                    \
        split4(pa1.x, pa1.y, pa1.z, pa1.w, h2, h3, l2, l3);                    \
        *(uint4*)(smc + (bufo) + st_off) = make_uint4(h0, h1, h2, h3);         \
        *(uint4*)(smc + (bufo) + PLANE_B + st_off) = make_uint4(l0, l1, l2, l3); \
        split4(pb0.x, pb0.y, pb0.z, pb0.w, h0, h1, l0, l1);                    \
        split4(pb1.x, pb1.y, pb1.z, pb1.w, h2, h3, l2, l3);                    \
        *(uint4*)(smc + (bufo) + 2 * PLANE_B + st_off) = make_uint4(h0, h1, h2, h3); \
        *(uint4*)(smc + (bufo) + 3 * PLANE_B + st_off) = make_uint4(l0, l1, l2, l3); \
    } while (0)

    LOADCHUNK(0);
    CVTSTORE(0);
    __syncthreads();

    for (int c = 0; c < 64; c++) {
        const uint32_t bufo = (uint32_t)(c & 1) * BUF_B;
        if (c < 63) LOADCHUNK(c + 1);

        uint32_t ah[4][4], al[4][4], bh[4][2], bl[4][2];
#pragma unroll
        for (int mi = 0; mi < 4; mi++) {
            ldmatrix_x4(ah[mi][0], ah[mi][1], ah[mi][2], ah[mi][3],
                        a_ld0 + bufo + mi * 768u);
            ldmatrix_x4(al[mi][0], al[mi][1], al[mi][2], al[mi][3],
                        a_ld0 + bufo + PLANE_B + mi * 768u);
        }
#pragma unroll
        for (int p = 0; p < 2; p++) {
            uint32_t t0, t1, t2, t3;
            ldmatrix_x4(t0, t1, t2, t3, b_ld0 + bufo + p * 768u);
            bh[p * 2][0] = t0;     bh[p * 2][1] = t2;
            bh[p * 2 + 1][0] = t1; bh[p * 2 + 1][1] = t3;
            ldmatrix_x4(t0, t1, t2, t3, b_ld0 + bufo + PLANE_B + p * 768u);
            bl[p * 2][0] = t0;     bl[p * 2][1] = t2;
            bl[p * 2 + 1][0] = t1; bl[p * 2 + 1][1] = t3;
        }

#pragma unroll
        for (int mi = 0; mi < 4; mi++)
#pragma unroll
            for (int ni = 0; ni < 4; ni++) {
                float* d = acc[mi][ni];
                mma_bf16(d, ah[mi][0], ah[mi][1], ah[mi][2], ah[mi][3],
                         bh[ni][0], bh[ni][1]);
                mma_bf16(d, ah[mi][0], ah[mi][1], ah[mi][2], ah[mi][3],
                         bl[ni][0], bl[ni][1]);
                mma_bf16(d, al[mi][0], al[mi][1], al[mi][2], al[mi][3],
                         bh[ni][0], bh[ni][1]);
            }

        __syncthreads();
        if (c < 63) {
            CVTSTORE(((uint32_t)((c + 1) & 1)) * BUF_B);
            __syncthreads();
        }
    }

#pragma unroll
    for (int mi = 0; mi < 4; mi++) {
#pragma unroll
        for (int ni = 0; ni < 4; ni++) {
            int m0 = bm + warp_m * 64 + mi * 16 + (lane >> 2);
            int n = bn + warp_n * 32 + ni * 8 + (lane & 3) * 2;
            float b0v = bias[n], b1v = bias[n + 1];
#pragma unroll
            for (int half = 0; half < 2; half++) {
                int m = m0 + half * 8;
                float2 v;
                v.x = acc[mi][ni][half * 2 + 0] + b0v;
                v.y = acc[mi][ni][half * 2 + 1] + b1v;
                if (head_split) {
                    int b = m >> 11;
                    int s = m & (SS - 1);
                    int h = n >> 6;
                    int hd = n & (HD - 1);
                    *(float2*)(C + (((size_t)(b * HH + h)) * SS + s) * HD + hd) = v;
                } else {
                    *(float2*)(C + (size_t)m * DD + n) = v;
                }
            }
        }
    }
#undef LOADCHUNK
#undef CVTSTORE
}

// ===========================================================================
// Mask compaction (unchanged)
// ===========================================================================
__global__ __launch_bounds__(1024) void compact_idx(
    const int* __restrict__ mask, int* __restrict__ idx, int* __restrict__ cnt)
{
    const int b = blockIdx.x;
    __shared__ int wsum[32];
    const int t = threadIdx.x;
    const int lane = t & 31;
    const int w = t >> 5;

    const int p0 = 2 * t, p1 = 2 * t + 1;
    const int m0 = mask[b * SS + p0] != 0;
    const int m1 = mask[b * SS + p1] != 0;
    const int local = m0 + m1;

    int v = local;
#pragma unroll
    for (int off = 1; off < 32; off <<= 1) {
        int u = __shfl_up_sync(0xffffffffu, v, off);
        if (lane >= off) v += u;
    }
    if (lane == 31) wsum[w] = v;
    __syncthreads();
    if (w == 0) {
        int s = wsum[lane];
#pragma unroll
        for (int off = 1; off < 32; off <<= 1) {
            int u = __shfl_up_sync(0xffffffffu, s, off);
            if (lane >= off) s += u;
        }
        wsum[lane] = s;
    }
    __syncthreads();

    const int base = (w > 0 ? wsum[w - 1] : 0) + (v - local);
    if (m0) idx[b * SS + base] = p0;
    if (m1) idx[b * SS + base + m0] = p1;
    if (t == 1023) cnt[b] = wsum[31];
}

// ===========================================================================
// Gather live K/V rows, convert to bf16 hi/lo planes; zero-pad to 128 mult.
// ===========================================================================
__global__ __launch_bounds__(256) void gather_kv(
    const float* __restrict__ K, const float* __restrict__ V,
    const int* __restrict__ idx, const int* __restrict__ cnt,
    __nv_bfloat16* __restrict__ Kh, __nv_bfloat16* __restrict__ Kl,
    __nv_bfloat16* __restrict__ Vh, __nv_bfloat16* __restrict__ Vl)
{
    const int b = blockIdx.z, h = blockIdx.y;
    const int j0 = blockIdx.x * 128;
    const int nlive = cnt[b];
    const int npad = (nlive + 127) & ~127;
    if (j0 >= npad) return;

    const size_t bh = (size_t)(b * HH + h) * SS;
    const int* ib = idx + b * SS;

    for (int t = threadIdx.x; t < 128 * 16; t += 256) {
        int j = j0 + (t >> 4);
        int c4 = (t & 15) * 4;
        float4 kv = make_float4(0.f, 0.f, 0.f, 0.f), vv = kv;
        if (j < nlive) {
            int src = ib[j];
            kv = *(const float4*)(K + (bh + src) * HD + c4);
            vv = *(const float4*)(V + (bh + src) * HD + c4);
        }
        uint32_t h0, h1, l0, l1;
        split4(kv.x, kv.y, kv.z, kv.w, h0, h1, l0, l1);
        *(uint2*)(Kh + (bh + j) * HD + c4) = make_uint2(h0, h1);
        *(uint2*)(Kl + (bh + j) * HD + c4) = make_uint2(l0, l1);
        split4(vv.x, vv.y, vv.z, vv.w, h0, h1, l0, l1);
        *(uint2*)(Vh + (bh + j) * HD + c4) = make_uint2(h0, h1);
        *(uint2*)(Vl + (bh + j) * HD + c4) = make_uint2(l0, l1);
    }
}

// ===========================================================================
// Tensor-core flash attention (bf16x3 QK^T and PV), 64-key tiles.
// 256 threads = 8 warps; warp w owns q rows [w*16, w*16+16).
// ===========================================================================
#define OFF_QH 0
#define OFF_QL 16384
#define OFF_KH 32768
#define OFF_KL 40960
#define OFF_VH 49152
#define OFF_VL 57344
#define ATTN_SMEM 65536

__global__ __launch_bounds__(256, 1) void attn_tc(
    const float* __restrict__ Qf,
    const __nv_bfloat16* __restrict__ Kh, const __nv_bfloat16* __restrict__ Kl,
    const __nv_bfloat16* __restrict__ Vh, const __nv_bfloat16* __restrict__ Vl,
    const int* __restrict__ cnt,
    float* __restrict__ Out)
{
    extern __shared__ char smb[];
    const uint32_t sbase = smem_u32(smb);

    const int tid = threadIdx.x;
    const int lane = tid & 31;
    const int w = tid >> 5;
    const int b = blockIdx.z, h = blockIdx.y;
    const int q0 = blockIdx.x * 128;
    const int nlive = cnt[b];
    const size_t bh = (size_t)(b * HH + h) * SS;

    // --- stage Q (fp32 -> bf16 hi/lo, swizzled) ---
    const float* Qb = Qf + (bh + q0) * HD;
#pragma unroll
    for (int it = 0; it < 8; it++) {
        int i = tid + it * 256;               // 0..2047
        int row = i >> 4, c4 = (i & 15) * 4;
        float4 v = *(const float4*)(Qb + (size_t)row * HD + c4);
        uint32_t h0, h1, l0, l1;
        split4(v.x, v.y, v.z, v.w, h0, h1, l0, l1);
        uint32_t sw = SW128((uint32_t)(row * 128 + c4 * 2));
        *(uint2*)(smb + OFF_QH + sw) = make_uint2(h0, h1);
        *(uint2*)(smb + OFF_QL + sw) = make_uint2(l0, l1);
    }
    __syncthreads();

    // --- preload Q fragments (per warp: rows w*16..+15, all 64 d) ---
    uint32_t qh[4][4], ql[4][4];
    {
        const int grp = lane >> 3;
        const int arow = w * 16 + (grp & 1) * 8 + (lane & 7);
        const int adb = (grp >> 1) * 16;
#pragma unroll
        for (int kc = 0; kc < 4; kc++) {
            uint32_t sw = SW128((uint32_t)(arow * 128 + kc * 32 + adb));
            ldmatrix_x4(qh[kc][0], qh[kc][1], qh[kc][2], qh[kc][3], sbase + OFF_QH + sw);
            ldmatrix_x4(ql[kc][0], ql[kc][1], ql[kc][2], ql[kc][3], sbase + OFF_QL + sw);
        }
    }

    float Oacc[8][4];
#pragma unroll
    for (int i = 0; i < 8; i++)
#pragma unroll
        for (int j = 0; j < 4; j++) Oacc[i][j] = 0.f;
    float m0r = -1e30f, m1r = -1e30f, l0r = 0.f, l1r = 0.f;

    // precomputed ldmatrix lane-address components
    const int grp = lane >> 3;
    // K b-frag: key = np*16 + (grp>>1)*8 + (lane&7); dbyte = kc*32 + (grp&1)*16
    const int k_keyoff = (grp >> 1) * 8 + (lane & 7);
    const int k_dboff = (grp & 1) * 16;
    // V b-frag(trans): key = kc*16 + (grp&1)*8 + (lane&7); hdbyte = np*32 + (grp>>1)*16
    const int v_keyoff = (grp & 1) * 8 + (lane & 7);
    const int v_hdoff = (grp >> 1) * 16;

    for (int kt = 0; kt < nlive; kt += 64) {
        __syncthreads();
        // --- load K/V hi/lo tile (64 rows x 64 bf16 each plane) ---
#pragma unroll
        for (int it = 0; it < 8; it++) {
            int i = tid + it * 256;           // 0..2047
            int plane = i >> 9;
            int idx = i & 511;
            int row = idx >> 3, ch = idx & 7;
            const __nv_bfloat16* src =
                (plane == 0) ? Kh : (plane == 1) ? Kl : (plane == 2) ? Vh : Vl;
            uint32_t dsto = (plane == 0) ? OFF_KH : (plane == 1) ? OFF_KL
                            : (plane == 2) ? OFF_VH : OFF_VL;
            uint4 d = *(const uint4*)(src + (bh + kt + row) * HD + ch * 8);
            *(uint4*)(smb + dsto + SW128((uint32_t)(row * 128 + ch * 16))) = d;
        }
        __syncthreads();

        // --- S = Q K^T (bf16x3) ---
        float sc[8][4];
#pragma unroll
        for (int i = 0; i < 8; i++)
#pragma unroll
            for (int j = 0; j < 4; j++) sc[i][j] = 0.f;

#pragma unroll
        for (int kc = 0; kc < 4; kc++) {
#pragma unroll
            for (int np = 0; np < 4; np++) {
                uint32_t swk = SW128((uint32_t)((np * 16 + k_keyoff) * 128 + kc * 32 + k_dboff));
                uint32_t kh0, kh1, kh2, kh3, kl0, kl1, kl2, kl3;
                ldmatrix_x4(kh0, kh1, kh2, kh3, sbase + OFF_KH + swk);
                ldmatrix_x4(kl0, kl1, kl2, kl3, sbase + OFF_KL + swk);
                mma_bf16(sc[2 * np], qh[kc][0], qh[kc][1], qh[kc][2], qh[kc][3], kh0, kh1);
                mma_bf16(sc[2 * np], qh[kc][0], qh[kc][1], qh[kc][2], qh[kc][3], kl0, kl1);
                mma_bf16(sc[2 * np], ql[kc][0], ql[kc][1], ql[kc][2], ql[kc][3], kh0, kh1);
                mma_bf16(sc[2 * np + 1], qh[kc][0], qh[kc][1], qh[kc][2], qh[kc][3], kh2, kh3);
                mma_bf16(sc[2 * np + 1], qh[kc][0], qh[kc][1], qh[kc][2], qh[kc][3], kl2, kl3);
                mma_bf16(sc[2 * np + 1], ql[kc][0], ql[kc][1], ql[kc][2], ql[kc][3], kh2, kh3);
            }
        }

        // --- online softmax (rows r=lane>>2 and r+8; cols over 8 ntiles) ---
        const bool tail = (kt + 64 > nlive);
        const int colbase = kt + (lane & 3) * 2;
#pragma unroll
        for (int i = 0; i < 8; i++) {
#pragma unroll
            for (int j = 0; j < 4; j++) sc[i][j] *= 0.125f;
        }
        if (tail) {
#pragma unroll
            for (int i = 0; i < 8; i++) {
                int c0 = colbase + i * 8;
                float bia0 = (c0 < nlive) ? 0.f : -1e9f;
                float bia1 = (c0 + 1 < nlive) ? 0.f : -1e9f;
                sc[i][0] += bia0; sc[i][1] += bia1;
                sc[i][2] += bia0; sc[i][3] += bia1;
            }
        }
        // row 0
        {
            float mx = sc[0][0];
#pragma unroll
            for (int i = 0; i < 8; i++) { mx = fmaxf(mx, sc[i][0]); mx = fmaxf(mx, sc[i][1]); }
            mx = fmaxf(mx, __shfl_xor_sync(0xffffffffu, mx, 1));
            mx = fmaxf(mx, __shfl_xor_sync(0xffffffffu, mx, 2));
            float nm = fmaxf(m0r, mx);
            float corr = __expf(m0r - nm);
            float ps = 0.f;
#pragma unroll
            for (int i = 0; i < 8; i++) {
                sc[i][0] = __expf(sc[i][0] - nm); ps += sc[i][0];
                sc[i][1] = __expf(sc[i][1] - nm); ps += sc[i][1];
            }
            ps += __shfl_xor_sync(0xffffffffu, ps, 1);
            ps += __shfl_xor_sync(0xffffffffu, ps, 2);
            l0r = l0r * corr + ps;
            m0r = nm;
#pragma unroll
            for (int i = 0; i < 8; i++) { Oacc[i][0] *= corr; Oacc[i][1] *= corr; }
        }
        // row 1
        {
            float mx = sc[0][2];
#pragma unroll
            for (int i = 0; i < 8; i++) { mx = fmaxf(mx, sc[i][2]); mx = fmaxf(mx, sc[i][3]); }
            mx = fmaxf(mx, __shfl_xor_sync(0xffffffffu, mx, 1));
            mx = fmaxf(mx, __shfl_xor_sync(0xffffffffu, mx, 2));
            float nm = fmaxf(m1r, mx);
            float corr = __expf(m1r - nm);
            float ps = 0.f;
#pragma unroll
            for (int i = 0; i < 8; i++) {
                sc[i][2] = __expf(sc[i][2] - nm); ps += sc[i][2];
                sc[i][3] = __expf(sc[i][3] - nm); ps += sc[i][3];
            }
            ps += __shfl_xor_sync(0xffffffffu, ps, 1);
            ps += __shfl_xor_sync(0xffffffffu, ps, 2);
            l1r = l1r * corr + ps;
            m1r = nm;
#pragma unroll
            for (int i = 0; i < 8; i++) { Oacc[i][2] *= corr; Oacc[i][3] *= corr; }
        }

        // --- O += P V (bf16x3), P fragments straight from sc registers ---
#pragma unroll
        for (int kc = 0; kc < 4; kc++) {
            uint32_t ah0, ah1, ah2, ah3, al0, al1, al2, al3;
            split4(sc[2 * kc][0], sc[2 * kc][1], sc[2 * kc][2], sc[2 * kc][3],
                   ah0, ah1, al0, al1);
            split4(sc[2 * kc + 1][0], sc[2 * kc + 1][1], sc[2 * kc + 1][2], sc[2 * kc + 1][3],
                   ah2, ah3, al2, al3);
#pragma unroll
            for (int np = 0; np < 4; np++) {
                uint32_t swv = SW128((uint32_t)((kc * 16 + v_keyoff) * 128 + np * 32 + v_hdoff));
                uint32_t vh0, vh1, vh2, vh3, vl0, vl1, vl2, vl3;
                ldmatrix_x4_trans(vh0, vh1, vh2, vh3, sbase + OFF_VH + swv);
                ldmatrix_x4_trans(vl0, vl1, vl2, vl3, sbase + OFF_VL + swv);
                mma_bf16(Oacc[2 * np], ah0, ah1, ah2, ah3, vh0, vh1);
                mma_bf16(Oacc[2 * np], ah0, ah1, ah2, ah3, vl0, vl1);
                mma_bf16(Oacc[2 * np], al0, al1, al2, al3, vh0, vh1);
                mma_bf16(Oacc[2 * np + 1], ah0, ah1, ah2, ah3, vh2, vh3);
                mma_bf16(Oacc[2 * np + 1], ah0, ah1, ah2, ah3, vl2, vl3);
                mma_bf16(Oacc[2 * np + 1], al0, al1, al2, al3, vh2, vh3);
            }
        }
    }

    // --- epilogue ---
    const float inv0 = 1.0f / l0r;
    const float inv1 = 1.0f / l1r;
    const int rg0 = q0 + w * 16 + (lane >> 2);
    const int rg1 = rg0 + 8;
    const int cb = h * HD + (lane & 3) * 2;
#pragma unroll
    for (int nt = 0; nt < 8; nt++) {
        int col = cb + nt * 8;
        float2 o0 = make_float2(Oacc[nt][0] * inv0, Oacc[nt][1] * inv0);
        float2 o1 = make_float2(Oacc[nt][2] * inv1, Oacc[nt][3] * inv1);
        *(float2*)(Out + ((size_t)(b * SS + rg0)) * DD + col) = o0;
        *(float2*)(Out + ((size_t)(b * SS + rg1)) * DD + col) = o1;
    }
}

// ---------------------------------------------------------------------------
extern "C" void kernel_launch(void* const* d_in, const int* in_sizes, int n_in,
                              void* d_out, int out_size)
{
    const float* xq = (const float*)d_in[0];
    const float* xk = (const float*)d_in[1];
    const float* xv = (const float*)d_in[2];
    const int*   mask = (const int*)d_in[3];
    const float* wq = (const float*)d_in[4];
    const float* bq = (const float*)d_in[5];
    const float* wk = (const float*)d_in[6];
    const float* bk = (const float*)d_in[7];
    const float* wv = (const float*)d_in[8];
    const float* bv = (const float*)d_in[9];
    const float* wo = (const float*)d_in[10];
    const float* bo = (const float*)d_in[11];
    float* out = (float*)d_out;

    float *Qp, *Kp, *Vp, *Ap;
    __nv_bfloat16 *Khp, *Klp, *Vhp, *Vlp;
    int *idxp, *cntp;
    cudaGetSymbolAddress((void**)&Qp, g_Q);
    cudaGetSymbolAddress((void**)&Kp, g_K);
    cudaGetSymbolAddress((void**)&Vp, g_V);
    cudaGetSymbolAddress((void**)&Ap, g_A);
    cudaGetSymbolAddress((void**)&Khp, g_Kh);
    cudaGetSymbolAddress((void**)&Klp, g_Kl);
    cudaGetSymbolAddress((void**)&Vhp, g_Vh);
    cudaGetSymbolAddress((void**)&Vlp, g_Vl);
    cudaGetSymbolAddress((void**)&idxp, g_idx);
    cudaGetSymbolAddress((void**)&cntp, g_cnt);

    cudaFuncSetAttribute(attn_tc,
                         cudaFuncAttributeMaxDynamicSharedMemorySize, ATTN_SMEM);
    cudaFuncSetAttribute(tc_gemm_bias,
                         cudaFuncAttributeMaxDynamicSharedMemorySize, GEMM_SMEM);

    dim3 ggrid(DD / 128, MM / 128);   // (8, 32)
    tc_gemm_bias<<<ggrid, 256, GEMM_SMEM>>>(xq, wq, bq, Qp, 1);
    tc_gemm_bias<<<ggrid, 256, GEMM_SMEM>>>(xk, wk, bk, Kp, 1);
    tc_gemm_bias<<<ggrid, 256, GEMM_SMEM>>>(xv, wv, bv, Vp, 1);

    compact_idx<<<BB, 1024>>>(mask, idxp, cntp);
    gather_kv<<<dim3(SS / 128, HH, BB), 256>>>(Kp, Vp, idxp, cntp, Khp, Klp, Vhp, Vlp);

    attn_tc<<<dim3(SS / 128, HH, BB), 256, ATTN_SMEM>>>(Qp, Khp, Klp, Vhp, Vlp, cntp, Ap);

    tc_gemm_bias<<<ggrid, 256, GEMM_SMEM>>>(Ap, wo, bo, out, 0);
}

// round 10
// speedup vs baseline: 4.8349x; 1.2680x over previous
#include <cuda_runtime.h>
#include <cuda_bf16.h>
#include <cstdint>

#define BB 2
#define SS 2048
#define DD 1024
#define HH 16
#define HD 64
#define MM (BB * SS)   // 4096 rows

// Scratch (allocation-free rule: __device__ globals)
__device__ __align__(16) float g_Q[BB * SS * DD];           // (B,H,S,HD) fp32
__device__ __align__(16) __nv_bfloat16 g_Kh[BB * SS * DD];  // compacted K hi
__device__ __align__(16) __nv_bfloat16 g_Kl[BB * SS * DD];  // compacted K lo
__device__ __align__(16) __nv_bfloat16 g_Vh[BB * SS * DD];  // compacted V hi
__device__ __align__(16) __nv_bfloat16 g_Vl[BB * SS * DD];  // compacted V lo
__device__ __align__(16) float g_A[BB * SS * DD];           // attn out (B,S,D)
__device__ int g_map[BB * SS];   // compacted j -> global source row (or -1)
__device__ int g_cnt[BB];

// ===========================================================================
// arch-portable tensor helpers
// ===========================================================================
__device__ __forceinline__ uint32_t smem_u32(const void* p) {
    uint32_t a;
    asm("{ .reg .u64 t; cvta.to.shared.u64 t, %1; cvt.u32.u64 %0, t; }"
        : "=r"(a) : "l"(p));
    return a;
}

__device__ __forceinline__ void ldmatrix_x4(uint32_t& r0, uint32_t& r1,
                                            uint32_t& r2, uint32_t& r3,
                                            uint32_t addr) {
    asm volatile("ldmatrix.sync.aligned.m8n8.x4.shared.b16 {%0,%1,%2,%3}, [%4];"
                 : "=r"(r0), "=r"(r1), "=r"(r2), "=r"(r3) : "r"(addr));
}

__device__ __forceinline__ void ldmatrix_x4_trans(uint32_t& r0, uint32_t& r1,
                                                  uint32_t& r2, uint32_t& r3,
                                                  uint32_t addr) {
    asm volatile("ldmatrix.sync.aligned.m8n8.x4.trans.shared.b16 {%0,%1,%2,%3}, [%4];"
                 : "=r"(r0), "=r"(r1), "=r"(r2), "=r"(r3) : "r"(addr));
}

__device__ __forceinline__ void mma_bf16(float* d,
                                         uint32_t a0, uint32_t a1, uint32_t a2, uint32_t a3,
                                         uint32_t b0, uint32_t b1) {
    asm volatile(
        "mma.sync.aligned.m16n8k16.row.col.f32.bf16.bf16.f32 "
        "{%0,%1,%2,%3}, {%4,%5,%6,%7}, {%8,%9}, {%0,%1,%2,%3};"
        : "+f"(d[0]), "+f"(d[1]), "+f"(d[2]), "+f"(d[3])
        : "r"(a0), "r"(a1), "r"(a2), "r"(a3), "r"(b0), "r"(b1));
}

__device__ __forceinline__ uint32_t pack2(float x, float y) {
    __nv_bfloat162 h = __floats2bfloat162_rn(x, y);
    return *reinterpret_cast<uint32_t*>(&h);
}

__device__ __forceinline__ void split4(float x, float y, float z, float w,
                                       uint32_t& h0, uint32_t& h1,
                                       uint32_t& l0, uint32_t& l1) {
    h0 = pack2(x, y); h1 = pack2(z, w);
    float fx = __uint_as_float(h0 << 16), fy = __uint_as_float(h0 & 0xffff0000u);
    float fz = __uint_as_float(h1 << 16), fw = __uint_as_float(h1 & 0xffff0000u);
    l0 = pack2(x - fx, y - fy); l1 = pack2(z - fz, w - fw);
}

#define SW128(o) ((o) ^ (((o) >> 3) & 0x70))

// ===========================================================================
// GEMM tiling constants (shared by both GEMM kernels)
// ===========================================================================
#define ASTR 24
#define PLANE_B (128 * ASTR * 2)
#define BUF_B   (4 * PLANE_B)
#define GEMM_SMEM (2 * BUF_B)

// Mainloop body shared via macros.
#define GEMM_PROLOG()                                                          \
    extern __shared__ char smc[];                                              \
    const uint32_t sb = smem_u32(smc);                                         \
    const int tid = threadIdx.x;                                               \
    const int lane = tid & 31;                                                 \
    const int wid = tid >> 5;                                                  \
    const int warp_m = wid & 1;                                                \
    const int warp_n = wid >> 1;                                               \
    const int bm = blockIdx.y * 128;                                           \
    const int bn = blockIdx.x * 128;                                           \
    const int r = tid >> 1;                                                    \
    const int c8 = (tid & 1) * 8;                                              \
    const uint32_t st_off = (uint32_t)(r * 48 + c8 * 2);                       \
    const int lrow = lane & 15;                                                \
    const int lbyte = (lane >> 4) * 16;                                        \
    const uint32_t a_ld0 = sb + (uint32_t)((warp_m * 64 + lrow) * 48 + lbyte); \
    const uint32_t b_ld0 = sb + 2 * PLANE_B + (uint32_t)((warp_n * 32 + lrow) * 48 + lbyte);

#define LOADCHUNK(cc)                                            \
    do {                                                         \
        if (live_row) {                                          \
            const float* ap = Ag + (cc) * 16;                    \
            pa0 = *(const float4*)(ap);                          \
            pa1 = *(const float4*)(ap + 4);                      \
        } else {                                                 \
            pa0 = make_float4(0.f, 0.f, 0.f, 0.f);               \
            pa1 = pa0;                                           \
        }                                                        \
        const float* wp = Wg + (cc) * 16;                        \
        pb0 = *(const float4*)(wp);                              \
        pb1 = *(const float4*)(wp + 4);                          \
    } while (0)

#define CVTSTORE(bufo)                                                         \
    do {                                                                       \
        uint32_t h0, h1, h2, h3, l0, l1, l2, l3;                               \
        split4(pa0.x, pa0.y, pa0.z, pa0.w, h0, h1, l0, l1);                    \
        split4(pa1.x, pa1.y, pa1.z, pa1.w, h2, h3, l2, l3);                    \
        *(uint4*)(smc + (bufo) + st_off) = make_uint4(h0, h1, h2, h3);         \
        *(uint4*)(smc + (bufo) + PLANE_B + st_off) = make_uint4(l0, l1, l2, l3); \
        split4(pb0.x, pb0.y, pb0.z, pb0.w, h0, h1, l0, l1);                    \
        split4(pb1.x, pb1.y, pb1.z, pb1.w, h2, h3, l2, l3);                    \
        *(uint4*)(smc + (bufo) + 2 * PLANE_B + st_off) = make_uint4(h0, h1, h2, h3); \
        *(uint4*)(smc + (bufo) + 3 * PLANE_B + st_off) = make_uint4(l0, l1, l2, l3); \
    } while (0)

#define GEMM_MAINLOOP()                                                        \
    float acc[4][4][4];                                                        \
    _Pragma("unroll") for (int i = 0; i < 4; i++)                              \
        _Pragma("unroll") for (int j = 0; j < 4; j++)                          \
            _Pragma("unroll") for (int k = 0; k < 4; k++) acc[i][j][k] = 0.f;  \
    float4 pa0, pa1, pb0, pb1;                                                 \
    LOADCHUNK(0);                                                              \
    CVTSTORE(0);                                                               \
    __syncthreads();                                                           \
    for (int c = 0; c < 64; c++) {                                             \
        const uint32_t bufo = (uint32_t)(c & 1) * BUF_B;                       \
        if (c < 63) LOADCHUNK(c + 1);                                          \
        uint32_t ah[4][4], al[4][4], bh[4][2], bl[4][2];                       \
        _Pragma("unroll") for (int mi = 0; mi < 4; mi++) {                     \
            ldmatrix_x4(ah[mi][0], ah[mi][1], ah[mi][2], ah[mi][3],            \
                        a_ld0 + bufo + mi * 768u);                             \
            ldmatrix_x4(al[mi][0], al[mi][1], al[mi][2], al[mi][3],            \
                        a_ld0 + bufo + PLANE_B + mi * 768u);                   \
        }                                                                      \
        _Pragma("unroll") for (int p = 0; p < 2; p++) {                        \
            uint32_t t0, t1, t2, t3;                                           \
            ldmatrix_x4(t0, t1, t2, t3, b_ld0 + bufo + p * 768u);              \
            bh[p * 2][0] = t0;     bh[p * 2][1] = t2;                          \
            bh[p * 2 + 1][0] = t1; bh[p * 2 + 1][1] = t3;                      \
            ldmatrix_x4(t0, t1, t2, t3, b_ld0 + bufo + PLANE_B + p * 768u);    \
            bl[p * 2][0] = t0;     bl[p * 2][1] = t2;                          \
            bl[p * 2 + 1][0] = t1; bl[p * 2 + 1][1] = t3;                      \
        }                                                                      \
        _Pragma("unroll") for (int mi = 0; mi < 4; mi++)                       \
            _Pragma("unroll") for (int ni = 0; ni < 4; ni++) {                 \
                float* d = acc[mi][ni];                                        \
                mma_bf16(d, ah[mi][0], ah[mi][1], ah[mi][2], ah[mi][3],        \
                         bh[ni][0], bh[ni][1]);                                \
                mma_bf16(d, ah[mi][0], ah[mi][1], ah[mi][2], ah[mi][3],        \
                         bl[ni][0], bl[ni][1]);                                \
                mma_bf16(d, al[mi][0], al[mi][1], al[mi][2], al[mi][3],        \
                         bh[ni][0], bh[ni][1]);                                \
            }                                                                  \
        __syncthreads();                                                       \
        if (c < 63) {                                                          \
            CVTSTORE(((uint32_t)((c + 1) & 1)) * BUF_B);                       \
            __syncthreads();                                                   \
        }                                                                      \
    }

// ===========================================================================
// Merged QKV projection GEMM.
// z = blockIdx.z: 0 -> Q (fp32 head-split out), 1 -> K, 2 -> V (compacted
// bf16 hi/lo planes out; A-rows gathered via rowmap; tiles beyond
// ceil128(nlive) skipped).
// ===========================================================================
__global__ __launch_bounds__(256, 1) void tc_gemm_qkv(
    const float* __restrict__ xq, const float* __restrict__ xk,
    const float* __restrict__ xv,
    const float* __restrict__ wq, const float* __restrict__ wk,
    const float* __restrict__ wv,
    const float* __restrict__ bq, const float* __restrict__ bk,
    const float* __restrict__ bv,
    float* __restrict__ Qout,
    __nv_bfloat16* __restrict__ Kh, __nv_bfloat16* __restrict__ Kl,
    __nv_bfloat16* __restrict__ Vh, __nv_bfloat16* __restrict__ Vl,
    const int* __restrict__ rowmap, const int* __restrict__ cnt)
{
    const int z = blockIdx.z;
    const float* A = (z == 0) ? xq : (z == 1) ? xk : xv;
    const float* W = (z == 0) ? wq : (z == 1) ? wk : wv;
    const float* bias = (z == 0) ? bq : (z == 1) ? bk : bv;

    GEMM_PROLOG();

    const int batch = bm >> 11;
    int nlive = SS;
    if (z > 0) {
        nlive = cnt[batch];
        if ((bm & (SS - 1)) >= ((nlive + 127) & ~127)) return;   // dead tile
    }

    bool live_row = true;
    const float* Ag;
    if (z == 0) {
        Ag = A + (size_t)(bm + r) * DD + c8;
    } else {
        int g = rowmap[bm + r];
        live_row = (g >= 0);
        Ag = A + (size_t)(live_row ? g : 0) * DD + c8;
    }
    const float* Wg = W + (size_t)(bn + r) * DD + c8;

    GEMM_MAINLOOP();

    // ---- epilogue ----
    __nv_bfloat16* Ph = (z == 1) ? Kh : Vh;
    __nv_bfloat16* Pl = (z == 1) ? Kl : Vl;
#pragma unroll
    for (int mi = 0; mi < 4; mi++) {
#pragma unroll
        for (int ni = 0; ni < 4; ni++) {
            int m0 = bm + warp_m * 64 + mi * 16 + (lane >> 2);
            int n = bn + warp_n * 32 + ni * 8 + (lane & 3) * 2;
            float b0v = bias[n], b1v = bias[n + 1];
#pragma unroll
            for (int half = 0; half < 2; half++) {
                int m = m0 + half * 8;
                float v0 = acc[mi][ni][half * 2 + 0];
                float v1 = acc[mi][ni][half * 2 + 1];
                int s = m & (SS - 1);
                int hh = n >> 6;
                int hd = n & (HD - 1);
                if (z == 0) {
                    float2 v = make_float2(v0 + b0v, v1 + b1v);
                    *(float2*)(Qout + (((size_t)(batch * HH + hh)) * SS + s) * HD + hd) = v;
                } else {
                    if (s < nlive) { v0 += b0v; v1 += b1v; }
                    else           { v0 = 0.f;  v1 = 0.f; }
                    uint32_t hi = pack2(v0, v1);
                    float f0 = __uint_as_float(hi << 16);
                    float f1 = __uint_as_float(hi & 0xffff0000u);
                    uint32_t lo = pack2(v0 - f0, v1 - f1);
                    size_t basei = (((size_t)(batch * HH + hh)) * SS + s) * HD + hd;
                    *(uint32_t*)(Ph + basei) = hi;
                    *(uint32_t*)(Pl + basei) = lo;
                }
            }
        }
    }
}

// ===========================================================================
// Output GEMM (fp32 in/out, plain layout) — unchanged math.
// ===========================================================================
__global__ __launch_bounds__(256, 1) void tc_gemm_bias(
    const float* __restrict__ A,
    const float* __restrict__ W,
    const float* __restrict__ bias,
    float* __restrict__ C)
{
    GEMM_PROLOG();
    const bool live_row = true;
    const float* Ag = A + (size_t)(bm + r) * DD + c8;
    const float* Wg = W + (size_t)(bn + r) * DD + c8;

    GEMM_MAINLOOP();

#pragma unroll
    for (int mi = 0; mi < 4; mi++) {
#pragma unroll
        for (int ni = 0; ni < 4; ni++) {
            int m0 = bm + warp_m * 64 + mi * 16 + (lane >> 2);
            int n = bn + warp_n * 32 + ni * 8 + (lane & 3) * 2;
            float b0v = bias[n], b1v = bias[n + 1];
#pragma unroll
            for (int half = 0; half < 2; half++) {
                int m = m0 + half * 8;
                float2 v;
                v.x = acc[mi][ni][half * 2 + 0] + b0v;
                v.y = acc[mi][ni][half * 2 + 1] + b1v;
                *(float2*)(C + (size_t)m * DD + n) = v;
            }
        }
    }
}

// ===========================================================================
// Mask compaction: rowmap[b*SS + j] = global source row (b*SS+src) for
// j < nlive, else -1. cnt[b] = nlive.
// ===========================================================================
__global__ __launch_bounds__(1024) void compact_idx(
    const int* __restrict__ mask, int* __restrict__ rowmap, int* __restrict__ cnt)
{
    const int b = blockIdx.x;
    __shared__ int wsum[32];
    const int t = threadIdx.x;
    const int lane = t & 31;
    const int w = t >> 5;

    const int p0 = 2 * t, p1 = 2 * t + 1;
    const int m0 = mask[b * SS + p0] != 0;
    const int m1 = mask[b * SS + p1] != 0;
    const int local = m0 + m1;

    // init pad marker everywhere (separated from scatter by scan's syncs)
    rowmap[b * SS + p0] = -1;
    rowmap[b * SS + p1] = -1;

    int v = local;
#pragma unroll
    for (int off = 1; off < 32; off <<= 1) {
        int u = __shfl_up_sync(0xffffffffu, v, off);
        if (lane >= off) v += u;
    }
    if (lane == 31) wsum[w] = v;
    __syncthreads();
    if (w == 0) {
        int s = wsum[lane];
#pragma unroll
        for (int off = 1; off < 32; off <<= 1) {
            int u = __shfl_up_sync(0xffffffffu, s, off);
            if (lane >= off) s += u;
        }
        wsum[lane] = s;
    }
    __syncthreads();

    const int base = (w > 0 ? wsum[w - 1] : 0) + (v - local);
    if (m0) rowmap[b * SS + base] = b * SS + p0;
    if (m1) rowmap[b * SS + base + m0] = b * SS + p1;
    if (t == 1023) cnt[b] = wsum[31];
}

// ===========================================================================
// Tensor-core flash attention (bf16x3 QK^T and PV), 64-key tiles. Unchanged.
// ===========================================================================
#define OFF_QH 0
#define OFF_QL 16384
#define OFF_KH 32768
#define OFF_KL 40960
#define OFF_VH 49152
#define OFF_VL 57344
#define ATTN_SMEM 65536

__global__ __launch_bounds__(256, 1) void attn_tc(
    const float* __restrict__ Qf,
    const __nv_bfloat16* __restrict__ Kh, const __nv_bfloat16* __restrict__ Kl,
    const __nv_bfloat16* __restrict__ Vh, const __nv_bfloat16* __restrict__ Vl,
    const int* __restrict__ cnt,
    float* __restrict__ Out)
{
    extern __shared__ char smb[];
    const uint32_t sbase = smem_u32(smb);

    const int tid = threadIdx.x;
    const int lane = tid & 31;
    const int w = tid >> 5;
    const int b = blockIdx.z, h = blockIdx.y;
    const int q0 = blockIdx.x * 128;
    const int nlive = cnt[b];
    const size_t bh = (size_t)(b * HH + h) * SS;

    const float* Qb = Qf + (bh + q0) * HD;
#pragma unroll
    for (int it = 0; it < 8; it++) {
        int i = tid + it * 256;
        int row = i >> 4, c4 = (i & 15) * 4;
        float4 v = *(const float4*)(Qb + (size_t)row * HD + c4);
        uint32_t h0, h1, l0, l1;
        split4(v.x, v.y, v.z, v.w, h0, h1, l0, l1);
        uint32_t sw = SW128((uint32_t)(row * 128 + c4 * 2));
        *(uint2*)(smb + OFF_QH + sw) = make_uint2(h0, h1);
        *(uint2*)(smb + OFF_QL + sw) = make_uint2(l0, l1);
    }
    __syncthreads();

    uint32_t qh[4][4], ql[4][4];
    {
        const int grp = lane >> 3;
        const int arow = w * 16 + (grp & 1) * 8 + (lane & 7);
        const int adb = (grp >> 1) * 16;
#pragma unroll
        for (int kc = 0; kc < 4; kc++) {
            uint32_t sw = SW128((uint32_t)(arow * 128 + kc * 32 + adb));
            ldmatrix_x4(qh[kc][0], qh[kc][1], qh[kc][2], qh[kc][3], sbase + OFF_QH + sw);
            ldmatrix_x4(ql[kc][0], ql[kc][1], ql[kc][2], ql[kc][3], sbase + OFF_QL + sw);
        }
    }

    float Oacc[8][4];
#pragma unroll
    for (int i = 0; i < 8; i++)
#pragma unroll
        for (int j = 0; j < 4; j++) Oacc[i][j] = 0.f;
    float m0r = -1e30f, m1r = -1e30f, l0r = 0.f, l1r = 0.f;

    const int grp = lane >> 3;
    const int k_keyoff = (grp >> 1) * 8 + (lane & 7);
    const int k_dboff = (grp & 1) * 16;
    const int v_keyoff = (grp & 1) * 8 + (lane & 7);
    const int v_hdoff = (grp >> 1) * 16;

    for (int kt = 0; kt < nlive; kt += 64) {
        __syncthreads();
#pragma unroll
        for (int it = 0; it < 8; it++) {
            int i = tid + it * 256;
            int plane = i >> 9;
            int idx = i & 511;
            int row = idx >> 3, ch = idx & 7;
            const __nv_bfloat16* src =
                (plane == 0) ? Kh : (plane == 1) ? Kl : (plane == 2) ? Vh : Vl;
            uint32_t dsto = (plane == 0) ? OFF_KH : (plane == 1) ? OFF_KL
                            : (plane == 2) ? OFF_VH : OFF_VL;
            uint4 d = *(const uint4*)(src + (bh + kt + row) * HD + ch * 8);
            *(uint4*)(smb + dsto + SW128((uint32_t)(row * 128 + ch * 16))) = d;
        }
        __syncthreads();

        float sc[8][4];
#pragma unroll
        for (int i = 0; i < 8; i++)
#pragma unroll
            for (int j = 0; j < 4; j++) sc[i][j] = 0.f;

#pragma unroll
        for (int kc = 0; kc < 4; kc++) {
#pragma unroll
            for (int np = 0; np < 4; np++) {
                uint32_t swk = SW128((uint32_t)((np * 16 + k_keyoff) * 128 + kc * 32 + k_dboff));
                uint32_t kh0, kh1, kh2, kh3, kl0, kl1, kl2, kl3;
                ldmatrix_x4(kh0, kh1, kh2, kh3, sbase + OFF_KH + swk);
                ldmatrix_x4(kl0, kl1, kl2, kl3, sbase + OFF_KL + swk);
                mma_bf16(sc[2 * np], qh[kc][0], qh[kc][1], qh[kc][2], qh[kc][3], kh0, kh1);
                mma_bf16(sc[2 * np], qh[kc][0], qh[kc][1], qh[kc][2], qh[kc][3], kl0, kl1);
                mma_bf16(sc[2 * np], ql[kc][0], ql[kc][1], ql[kc][2], ql[kc][3], kh0, kh1);
                mma_bf16(sc[2 * np + 1], qh[kc][0], qh[kc][1], qh[kc][2], qh[kc][3], kh2, kh3);
                mma_bf16(sc[2 * np + 1], qh[kc][0], qh[kc][1], qh[kc][2], qh[kc][3], kl2, kl3);
                mma_bf16(sc[2 * np + 1], ql[kc][0], ql[kc][1], ql[kc][2], ql[kc][3], kh2, kh3);
            }
        }

        const bool tail = (kt + 64 > nlive);
        const int colbase = kt + (lane & 3) * 2;
#pragma unroll
        for (int i = 0; i < 8; i++) {
#pragma unroll
            for (int j = 0; j < 4; j++) sc[i][j] *= 0.125f;
        }
        if (tail) {
#pragma unroll
            for (int i = 0; i < 8; i++) {
                int c0 = colbase + i * 8;
                float bia0 = (c0 < nlive) ? 0.f : -1e9f;
                float bia1 = (c0 + 1 < nlive) ? 0.f : -1e9f;
                sc[i][0] += bia0; sc[i][1] += bia1;
                sc[i][2] += bia0; sc[i][3] += bia1;
            }
        }
        {
            float mx = sc[0][0];
#pragma unroll
            for (int i = 0; i < 8; i++) { mx = fmaxf(mx, sc[i][0]); mx = fmaxf(mx, sc[i][1]); }
            mx = fmaxf(mx, __shfl_xor_sync(0xffffffffu, mx, 1));
            mx = fmaxf(mx, __shfl_xor_sync(0xffffffffu, mx, 2));
            float nm = fmaxf(m0r, mx);
            float corr = __expf(m0r - nm);
            float ps = 0.f;
#pragma unroll
            for (int i = 0; i < 8; i++) {
                sc[i][0] = __expf(sc[i][0] - nm); ps += sc[i][0];
                sc[i][1] = __expf(sc[i][1] - nm); ps += sc[i][1];
            }
            ps += __shfl_xor_sync(0xffffffffu, ps, 1);
            ps += __shfl_xor_sync(0xffffffffu, ps, 2);
            l0r = l0r * corr + ps;
            m0r = nm;
#pragma unroll
            for (int i = 0; i < 8; i++) { Oacc[i][0] *= corr; Oacc[i][1] *= corr; }
        }
        {
            float mx = sc[0][2];
#pragma unroll
            for (int i = 0; i < 8; i++) { mx = fmaxf(mx, sc[i][2]); mx = fmaxf(mx, sc[i][3]); }
            mx = fmaxf(mx, __shfl_xor_sync(0xffffffffu, mx, 1));
            mx = fmaxf(mx, __shfl_xor_sync(0xffffffffu, mx, 2));
            float nm = fmaxf(m1r, mx);
            float corr = __expf(m1r - nm);
            float ps = 0.f;
#pragma unroll
            for (int i = 0; i < 8; i++) {
                sc[i][2] = __expf(sc[i][2] - nm); ps += sc[i][2];
                sc[i][3] = __expf(sc[i][3] - nm); ps += sc[i][3];
            }
            ps += __shfl_xor_sync(0xffffffffu, ps, 1);
            ps += __shfl_xor_sync(0xffffffffu, ps, 2);
            l1r = l1r * corr + ps;
            m1r = nm;
#pragma unroll
            for (int i = 0; i < 8; i++) { Oacc[i][2] *= corr; Oacc[i][3] *= corr; }
        }

#pragma unroll
        for (int kc = 0; kc < 4; kc++) {
            uint32_t ah0, ah1, ah2, ah3, al0, al1, al2, al3;
            split4(sc[2 * kc][0], sc[2 * kc][1], sc[2 * kc][2], sc[2 * kc][3],
                   ah0, ah1, al0, al1);
            split4(sc[2 * kc + 1][0], sc[2 * kc + 1][1], sc[2 * kc + 1][2], sc[2 * kc + 1][3],
                   ah2, ah3, al2, al3);
#pragma unroll
            for (int np = 0; np < 4; np++) {
                uint32_t swv = SW128((uint32_t)((kc * 16 + v_keyoff) * 128 + np * 32 + v_hdoff));
                uint32_t vh0, vh1, vh2, vh3, vl0, vl1, vl2, vl3;
                ldmatrix_x4_trans(vh0, vh1, vh2, vh3, sbase + OFF_VH + swv);
                ldmatrix_x4_trans(vl0, vl1, vl2, vl3, sbase + OFF_VL + swv);
                mma_bf16(Oacc[2 * np], ah0, ah1, ah2, ah3, vh0, vh1);
                mma_bf16(Oacc[2 * np], ah0, ah1, ah2, ah3, vl0, vl1);
                mma_bf16(Oacc[2 * np], al0, al1, al2, al3, vh0, vh1);
                mma_bf16(Oacc[2 * np + 1], ah0, ah1, ah2, ah3, vh2, vh3);
                mma_bf16(Oacc[2 * np + 1], ah0, ah1, ah2, ah3, vl2, vl3);
                mma_bf16(Oacc[2 * np + 1], al0, al1, al2, al3, vh2, vh3);
            }
        }
    }

    const float inv0 = 1.0f / l0r;
    const float inv1 = 1.0f / l1r;
    const int rg0 = q0 + w * 16 + (lane >> 2);
    const int rg1 = rg0 + 8;
    const int cb = h * HD + (lane & 3) * 2;
#pragma unroll
    for (int nt = 0; nt < 8; nt++) {
        int col = cb + nt * 8;
        float2 o0 = make_float2(Oacc[nt][0] * inv0, Oacc[nt][1] * inv0);
        float2 o1 = make_float2(Oacc[nt][2] * inv1, Oacc[nt][3] * inv1);
        *(float2*)(Out + ((size_t)(b * SS + rg0)) * DD + col) = o0;
        *(float2*)(Out + ((size_t)(b * SS + rg1)) * DD + col) = o1;
    }
}

// ---------------------------------------------------------------------------
extern "C" void kernel_launch(void* const* d_in, const int* in_sizes, int n_in,
                              void* d_out, int out_size)
{
    const float* xq = (const float*)d_in[0];
    const float* xk = (const float*)d_in[1];
    const float* xv = (const float*)d_in[2];
    const int*   mask = (const int*)d_in[3];
    const float* wq = (const float*)d_in[4];
    const float* bq = (const float*)d_in[5];
    const float* wk = (const float*)d_in[6];
    const float* bk = (const float*)d_in[7];
    const float* wv = (const float*)d_in[8];
    const float* bv = (const float*)d_in[9];
    const float* wo = (const float*)d_in[10];
    const float* bo = (const float*)d_in[11];
    float* out = (float*)d_out;

    float *Qp, *Ap;
    __nv_bfloat16 *Khp, *Klp, *Vhp, *Vlp;
    int *mapp, *cntp;
    cudaGetSymbolAddress((void**)&Qp, g_Q);
    cudaGetSymbolAddress((void**)&Ap, g_A);
    cudaGetSymbolAddress((void**)&Khp, g_Kh);
    cudaGetSymbolAddress((void**)&Klp, g_Kl);
    cudaGetSymbolAddress((void**)&Vhp, g_Vh);
    cudaGetSymbolAddress((void**)&Vlp, g_Vl);
    cudaGetSymbolAddress((void**)&mapp, g_map);
    cudaGetSymbolAddress((void**)&cntp, g_cnt);

    cudaFuncSetAttribute(attn_tc,
                         cudaFuncAttributeMaxDynamicSharedMemorySize, ATTN_SMEM);
    cudaFuncSetAttribute(tc_gemm_qkv,
                         cudaFuncAttributeMaxDynamicSharedMemorySize, GEMM_SMEM);
    cudaFuncSetAttribute(tc_gemm_bias,
                         cudaFuncAttributeMaxDynamicSharedMemorySize, GEMM_SMEM);

    compact_idx<<<BB, 1024>>>(mask, mapp, cntp);

    tc_gemm_qkv<<<dim3(DD / 128, MM / 128, 3), 256, GEMM_SMEM>>>(
        xq, xk, xv, wq, wk, wv, bq, bk, bv,
        Qp, Khp, Klp, Vhp, Vlp, mapp, cntp);

    attn_tc<<<dim3(SS / 128, HH, BB), 256, ATTN_SMEM>>>(Qp, Khp, Klp, Vhp, Vlp, cntp, Ap);

    tc_gemm_bias<<<dim3(DD / 128, MM / 128), 256, GEMM_SMEM>>>(Ap, wo, bo, out);
}

// round 11
// speedup vs baseline: 5.0048x; 1.0351x over previous
#include <cuda_runtime.h>
#include <cuda_bf16.h>
#include <cstdint>

#define BB 2
#define SS 2048
#define DD 1024
#define HH 16
#define HD 64
#define MM (BB * SS)   // 4096 rows

// Scratch (allocation-free rule: __device__ globals)
__device__ __align__(16) float g_Q[MM * DD];                  // (B,H,S,HD) fp32
__device__ __align__(16) __nv_bfloat16 g_Xh[3 * MM * DD];     // xq,xk,xv hi
__device__ __align__(16) __nv_bfloat16 g_Xl[3 * MM * DD];     // xq,xk,xv lo
__device__ __align__(16) __nv_bfloat16 g_Wh[4 * DD * DD];     // wq,wk,wv,wo hi
__device__ __align__(16) __nv_bfloat16 g_Wl[4 * DD * DD];     // wq,wk,wv,wo lo
__device__ __align__(16) __nv_bfloat16 g_Kh[MM * DD];         // compacted K hi
__device__ __align__(16) __nv_bfloat16 g_Kl[MM * DD];
__device__ __align__(16) __nv_bfloat16 g_Vh[MM * DD];
__device__ __align__(16) __nv_bfloat16 g_Vl[MM * DD];
__device__ __align__(16) __nv_bfloat16 g_Ah[MM * DD];         // attn out hi (B,S,D)
__device__ __align__(16) __nv_bfloat16 g_Al[MM * DD];         // attn out lo
__device__ int g_map[BB * SS];
__device__ int g_cnt[BB];

// ===========================================================================
// helpers
// ===========================================================================
__device__ __forceinline__ uint32_t smem_u32(const void* p) {
    uint32_t a;
    asm("{ .reg .u64 t; cvta.to.shared.u64 t, %1; cvt.u32.u64 %0, t; }"
        : "=r"(a) : "l"(p));
    return a;
}

__device__ __forceinline__ void ldmatrix_x4(uint32_t& r0, uint32_t& r1,
                                            uint32_t& r2, uint32_t& r3,
                                            uint32_t addr) {
    asm volatile("ldmatrix.sync.aligned.m8n8.x4.shared.b16 {%0,%1,%2,%3}, [%4];"
                 : "=r"(r0), "=r"(r1), "=r"(r2), "=r"(r3) : "r"(addr));
}

__device__ __forceinline__ void ldmatrix_x4_trans(uint32_t& r0, uint32_t& r1,
                                                  uint32_t& r2, uint32_t& r3,
                                                  uint32_t addr) {
    asm volatile("ldmatrix.sync.aligned.m8n8.x4.trans.shared.b16 {%0,%1,%2,%3}, [%4];"
                 : "=r"(r0), "=r"(r1), "=r"(r2), "=r"(r3) : "r"(addr));
}

__device__ __forceinline__ void mma_bf16(float* d,
                                         uint32_t a0, uint32_t a1, uint32_t a2, uint32_t a3,
                                         uint32_t b0, uint32_t b1) {
    asm volatile(
        "mma.sync.aligned.m16n8k16.row.col.f32.bf16.bf16.f32 "
        "{%0,%1,%2,%3}, {%4,%5,%6,%7}, {%8,%9}, {%0,%1,%2,%3};"
        : "+f"(d[0]), "+f"(d[1]), "+f"(d[2]), "+f"(d[3])
        : "r"(a0), "r"(a1), "r"(a2), "r"(a3), "r"(b0), "r"(b1));
}

__device__ __forceinline__ uint32_t pack2(float x, float y) {
    __nv_bfloat162 h = __floats2bfloat162_rn(x, y);
    return *reinterpret_cast<uint32_t*>(&h);
}

__device__ __forceinline__ void split4(float x, float y, float z, float w,
                                       uint32_t& h0, uint32_t& h1,
                                       uint32_t& l0, uint32_t& l1) {
    h0 = pack2(x, y); h1 = pack2(z, w);
    float fx = __uint_as_float(h0 << 16), fy = __uint_as_float(h0 & 0xffff0000u);
    float fz = __uint_as_float(h1 << 16), fw = __uint_as_float(h1 & 0xffff0000u);
    l0 = pack2(x - fx, y - fy); l1 = pack2(z - fz, w - fw);
}

#define SW128(o) ((o) ^ (((o) >> 3) & 0x70))

// ===========================================================================
// Conversion kernels: fp32 -> bf16 hi/lo planes
// ===========================================================================
__global__ __launch_bounds__(256) void cvt_x(
    const float* __restrict__ x0, const float* __restrict__ x1,
    const float* __restrict__ x2,
    __nv_bfloat16* __restrict__ H, __nv_bfloat16* __restrict__ L)
{
    const float* src = (blockIdx.z == 0) ? x0 : (blockIdx.z == 1) ? x1 : x2;
    const size_t base = (size_t)blockIdx.z * MM * DD;
    const size_t i = (size_t)blockIdx.x * 256 + threadIdx.x;   // float4 idx
    float4 v = *((const float4*)src + i);
    uint32_t h0, h1, l0, l1;
    split4(v.x, v.y, v.z, v.w, h0, h1, l0, l1);
    *(uint2*)(H + base + i * 4) = make_uint2(h0, h1);
    *(uint2*)(L + base + i * 4) = make_uint2(l0, l1);
}

__global__ __launch_bounds__(256) void cvt_w(
    const float* __restrict__ w0, const float* __restrict__ w1,
    const float* __restrict__ w2, const float* __restrict__ w3,
    __nv_bfloat16* __restrict__ H, __nv_bfloat16* __restrict__ L)
{
    const float* src = (blockIdx.z == 0) ? w0 : (blockIdx.z == 1) ? w1
                       : (blockIdx.z == 2) ? w2 : w3;
    const size_t base = (size_t)blockIdx.z * DD * DD;
    const size_t i = (size_t)blockIdx.x * 256 + threadIdx.x;
    float4 v = *((const float4*)src + i);
    uint32_t h0, h1, l0, l1;
    split4(v.x, v.y, v.z, v.w, h0, h1, l0, l1);
    *(uint2*)(H + base + i * 4) = make_uint2(h0, h1);
    *(uint2*)(L + base + i * 4) = make_uint2(l0, l1);
}

// ===========================================================================
// Pipelined bf16x3 GEMM: 128x128 tile, K-chunk 16, 3-stage cp.async.
// smem stage: Ahi/Alo/Bhi/Blo planes, 128 rows x 48B each.
// ===========================================================================
#define ASTR 24
#define PLANE_B (128 * ASTR * 2)       // 6144
#define CHUNK_B (4 * PLANE_B)          // 24576
#define PIPE_S 3
#define GEMM_SMEM_P (PIPE_S * CHUNK_B) // 73728

#define GEMM_VARS()                                                            \
    extern __shared__ char smc[];                                              \
    const uint32_t sb = smem_u32(smc);                                         \
    const int tid = threadIdx.x;                                               \
    const int lane = tid & 31;                                                 \
    const int wid = tid >> 5;                                                  \
    const int warp_m = wid & 1;                                                \
    const int warp_n = wid >> 1;                                               \
    const int bm = blockIdx.y * 128;                                           \
    const int bn = blockIdx.x * 128;                                           \
    const int r = tid >> 1;                                                    \
    const int hf = tid & 1;                                                    \
    const uint32_t st16 = (uint32_t)(r * 48 + hf * 16);                        \
    const uint32_t aoff = (uint32_t)((warp_m * 64 + (lane & 15)) * 48 + (lane >> 4) * 16); \
    const uint32_t boff = (uint32_t)((warp_n * 32 + (lane & 15)) * 48 + (lane >> 4) * 16);

#define ISSUE_CHUNK(cc, stg)                                                   \
    do {                                                                       \
        uint32_t dst_ = sb + (uint32_t)(stg) * CHUNK_B + st16;                 \
        const char* s0_ = pAh + (size_t)(cc) * 32;                             \
        const char* s1_ = pAl + (size_t)(cc) * 32;                             \
        const char* s2_ = pBh + (size_t)(cc) * 32;                             \
        const char* s3_ = pBl + (size_t)(cc) * 32;                             \
        asm volatile("cp.async.cg.shared.global [%0], [%1], 16, %2;"           \
                     :: "r"(dst_), "l"(s0_), "r"(asz) : "memory");             \
        asm volatile("cp.async.cg.shared.global [%0], [%1], 16, %2;"           \
                     :: "r"(dst_ + PLANE_B), "l"(s1_), "r"(asz) : "memory");   \
        asm volatile("cp.async.cg.shared.global [%0], [%1], 16;"               \
                     :: "r"(dst_ + 2 * PLANE_B), "l"(s2_) : "memory");         \
        asm volatile("cp.async.cg.shared.global [%0], [%1], 16;"               \
                     :: "r"(dst_ + 3 * PLANE_B), "l"(s3_) : "memory");         \
        asm volatile("cp.async.commit_group;" ::: "memory");                   \
    } while (0)

#define COMPUTE_CHUNK(base_)                                                   \
    do {                                                                       \
        uint32_t bh[4][2], bl[4][2];                                           \
        _Pragma("unroll") for (int p = 0; p < 2; p++) {                        \
            uint32_t t0, t1, t2, t3;                                           \
            ldmatrix_x4(t0, t1, t2, t3, (base_) + 2 * PLANE_B + boff + p * 768u); \
            bh[p * 2][0] = t0;     bh[p * 2][1] = t2;                          \
            bh[p * 2 + 1][0] = t1; bh[p * 2 + 1][1] = t3;                      \
            ldmatrix_x4(t0, t1, t2, t3, (base_) + 3 * PLANE_B + boff + p * 768u); \
            bl[p * 2][0] = t0;     bl[p * 2][1] = t2;                          \
            bl[p * 2 + 1][0] = t1; bl[p * 2 + 1][1] = t3;                      \
        }                                                                      \
        _Pragma("unroll") for (int mi = 0; mi < 4; mi++) {                     \
            uint32_t a0, a1, a2, a3, c0, c1, c2, c3;                           \
            ldmatrix_x4(a0, a1, a2, a3, (base_) + aoff + mi * 768u);           \
            ldmatrix_x4(c0, c1, c2, c3, (base_) + PLANE_B + aoff + mi * 768u); \
            _Pragma("unroll") for (int ni = 0; ni < 4; ni++) {                 \
                float* d = acc[mi][ni];                                        \
                mma_bf16(d, a0, a1, a2, a3, bh[ni][0], bh[ni][1]);             \
                mma_bf16(d, a0, a1, a2, a3, bl[ni][0], bl[ni][1]);             \
                mma_bf16(d, c0, c1, c2, c3, bh[ni][0], bh[ni][1]);             \
            }                                                                  \
        }                                                                      \
    } while (0)

#define PIPE_MAINLOOP()                                                        \
    ISSUE_CHUNK(0, 0);                                                         \
    ISSUE_CHUNK(1, 1);                                                         \
    for (int c = 0; c < 64; c++) {                                             \
        if (c == 63) { asm volatile("cp.async.wait_group 0;" ::: "memory"); }  \
        else         { asm volatile("cp.async.wait_group 1;" ::: "memory"); }  \
        __syncthreads();                                                       \
        if (c < 62) ISSUE_CHUNK(c + 2, (c + 2) % 3);                           \
        const uint32_t cbase_ = sb + (uint32_t)(c % 3) * CHUNK_B;              \
        COMPUTE_CHUNK(cbase_);                                                 \
    }

// ===========================================================================
// Merged QKV projection GEMM (bf16-plane inputs).
// z: 0 -> Q (fp32 head-split out), 1 -> K, 2 -> V (compacted bf16 planes).
// ===========================================================================
__global__ __launch_bounds__(256, 2) void tc_gemm_qkv(
    const __nv_bfloat16* __restrict__ Xh, const __nv_bfloat16* __restrict__ Xl,
    const __nv_bfloat16* __restrict__ Wh, const __nv_bfloat16* __restrict__ Wl,
    const float* __restrict__ bq, const float* __restrict__ bk,
    const float* __restrict__ bv,
    float* __restrict__ Qout,
    __nv_bfloat16* __restrict__ Kh, __nv_bfloat16* __restrict__ Kl,
    __nv_bfloat16* __restrict__ Vh, __nv_bfloat16* __restrict__ Vl,
    const int* __restrict__ rowmap, const int* __restrict__ cnt)
{
    const int z = blockIdx.z;
    GEMM_VARS();

    const int batch = bm >> 11;
    int nlive = SS;
    if (z > 0) {
        nlive = cnt[batch];
        if ((bm & (SS - 1)) >= ((nlive + 127) & ~127)) return;   // dead tile
    }

    uint32_t asz = 16;
    int gr;
    if (z == 0) {
        gr = bm + r;
    } else {
        int g = rowmap[bm + r];
        asz = (g >= 0) ? 16u : 0u;
        gr = (g >= 0) ? g : 0;
    }
    const __nv_bfloat16* Xph = Xh + (size_t)z * MM * DD;
    const __nv_bfloat16* Xpl = Xl + (size_t)z * MM * DD;
    const __nv_bfloat16* Wph = Wh + (size_t)z * DD * DD;
    const __nv_bfloat16* Wpl = Wl + (size_t)z * DD * DD;
    const float* bias = (z == 0) ? bq : (z == 1) ? bk : bv;

    const char* pAh = (const char*)(Xph + (size_t)gr * DD) + hf * 16;
    const char* pAl = (const char*)(Xpl + (size_t)gr * DD) + hf * 16;
    const char* pBh = (const char*)(Wph + (size_t)(bn + r) * DD) + hf * 16;
    const char* pBl = (const char*)(Wpl + (size_t)(bn + r) * DD) + hf * 16;

    float acc[4][4][4];
#pragma unroll
    for (int i = 0; i < 4; i++)
#pragma unroll
        for (int j = 0; j < 4; j++)
#pragma unroll
            for (int k = 0; k < 4; k++) acc[i][j][k] = 0.f;

    PIPE_MAINLOOP();

    // ---- epilogue ----
    __nv_bfloat16* Ph = (z == 1) ? Kh : Vh;
    __nv_bfloat16* Pl = (z == 1) ? Kl : Vl;
#pragma unroll
    for (int mi = 0; mi < 4; mi++) {
#pragma unroll
        for (int ni = 0; ni < 4; ni++) {
            int m0 = bm + warp_m * 64 + mi * 16 + (lane >> 2);
            int n = bn + warp_n * 32 + ni * 8 + (lane & 3) * 2;
            float b0v = bias[n], b1v = bias[n + 1];
#pragma unroll
            for (int half = 0; half < 2; half++) {
                int m = m0 + half * 8;
                float v0 = acc[mi][ni][half * 2 + 0];
                float v1 = acc[mi][ni][half * 2 + 1];
                int s = m & (SS - 1);
                int hh = n >> 6;
                int hd = n & (HD - 1);
                if (z == 0) {
                    float2 v = make_float2(v0 + b0v, v1 + b1v);
                    *(float2*)(Qout + (((size_t)(batch * HH + hh)) * SS + s) * HD + hd) = v;
                } else {
                    if (s < nlive) { v0 += b0v; v1 += b1v; }
                    else           { v0 = 0.f;  v1 = 0.f; }
                    uint32_t hi = pack2(v0, v1);
                    float f0 = __uint_as_float(hi << 16);
                    float f1 = __uint_as_float(hi & 0xffff0000u);
                    uint32_t lo = pack2(v0 - f0, v1 - f1);
                    size_t basei = (((size_t)(batch * HH + hh)) * SS + s) * HD + hd;
                    *(uint32_t*)(Ph + basei) = hi;
                    *(uint32_t*)(Pl + basei) = lo;
                }
            }
        }
    }
}

// ===========================================================================
// Output GEMM: A = attn-out planes, W = wo planes, fp32 out.
// ===========================================================================
__global__ __launch_bounds__(256, 2) void tc_gemm_out(
    const __nv_bfloat16* __restrict__ Ah, const __nv_bfloat16* __restrict__ Al,
    const __nv_bfloat16* __restrict__ Wh, const __nv_bfloat16* __restrict__ Wl,
    const float* __restrict__ bias, float* __restrict__ C)
{
    GEMM_VARS();
    const uint32_t asz = 16;
    const char* pAh = (const char*)(Ah + (size_t)(bm + r) * DD) + hf * 16;
    const char* pAl = (const char*)(Al + (size_t)(bm + r) * DD) + hf * 16;
    const char* pBh = (const char*)(Wh + (size_t)(3 * DD * DD) + (size_t)(bn + r) * DD) + hf * 16;
    const char* pBl = (const char*)(Wl + (size_t)(3 * DD * DD) + (size_t)(bn + r) * DD) + hf * 16;

    float acc[4][4][4];
#pragma unroll
    for (int i = 0; i < 4; i++)
#pragma unroll
        for (int j = 0; j < 4; j++)
#pragma unroll
            for (int k = 0; k < 4; k++) acc[i][j][k] = 0.f;

    PIPE_MAINLOOP();

#pragma unroll
    for (int mi = 0; mi < 4; mi++) {
#pragma unroll
        for (int ni = 0; ni < 4; ni++) {
            int m0 = bm + warp_m * 64 + mi * 16 + (lane >> 2);
            int n = bn + warp_n * 32 + ni * 8 + (lane & 3) * 2;
            float b0v = bias[n], b1v = bias[n + 1];
#pragma unroll
            for (int half = 0; half < 2; half++) {
                int m = m0 + half * 8;
                float2 v;
                v.x = acc[mi][ni][half * 2 + 0] + b0v;
                v.y = acc[mi][ni][half * 2 + 1] + b1v;
                *(float2*)(C + (size_t)m * DD + n) = v;
            }
        }
    }
}

// ===========================================================================
// Mask compaction (unchanged)
// ===========================================================================
__global__ __launch_bounds__(1024) void compact_idx(
    const int* __restrict__ mask, int* __restrict__ rowmap, int* __restrict__ cnt)
{
    const int b = blockIdx.x;
    __shared__ int wsum[32];
    const int t = threadIdx.x;
    const int lane = t & 31;
    const int w = t >> 5;

    const int p0 = 2 * t, p1 = 2 * t + 1;
    const int m0 = mask[b * SS + p0] != 0;
    const int m1 = mask[b * SS + p1] != 0;
    const int local = m0 + m1;

    rowmap[b * SS + p0] = -1;
    rowmap[b * SS + p1] = -1;

    int v = local;
#pragma unroll
    for (int off = 1; off < 32; off <<= 1) {
        int u = __shfl_up_sync(0xffffffffu, v, off);
        if (lane >= off) v += u;
    }
    if (lane == 31) wsum[w] = v;
    __syncthreads();
    if (w == 0) {
        int s = wsum[lane];
#pragma unroll
        for (int off = 1; off < 32; off <<= 1) {
            int u = __shfl_up_sync(0xffffffffu, s, off);
            if (lane >= off) s += u;
        }
        wsum[lane] = s;
    }
    __syncthreads();

    const int base = (w > 0 ? wsum[w - 1] : 0) + (v - local);
    if (m0) rowmap[b * SS + base] = b * SS + p0;
    if (m1) rowmap[b * SS + base + m0] = b * SS + p1;
    if (t == 1023) cnt[b] = wsum[31];
}

// ===========================================================================
// Tensor-core flash attention, 2-stage cp.async K/V pipeline.
// smem: Qh 16K | Ql 16K | 2 KV stages x (Kh 8K | Kl 8K | Vh 8K | Vl 8K).
// ===========================================================================
#define OFF_QH 0
#define OFF_QL 16384
#define OFF_KV 32768
#define ATTN_SMEM (32768 + 2 * 32768)   // 98304

#define ISSUE_KV(ktv, stg)                                                     \
    do {                                                                       \
        _Pragma("unroll") for (int it = 0; it < 8; it++) {                     \
            int i_ = tid + it * 256;                                           \
            int plane_ = i_ >> 9;                                              \
            int idx_ = i_ & 511;                                               \
            int row_ = idx_ >> 3, ch_ = idx_ & 7;                              \
            const __nv_bfloat16* sp_ =                                         \
                (plane_ == 0) ? Kh : (plane_ == 1) ? Kl : (plane_ == 2) ? Vh : Vl; \
            const char* src_ = (const char*)(sp_ + (bh + (ktv) + row_) * HD) + ch_ * 16; \
            uint32_t dst_ = sbase + (uint32_t)(OFF_KV + (stg) * 32768 + plane_ * 8192 \
                            + SW128((uint32_t)(row_ * 128 + ch_ * 16)));       \
            asm volatile("cp.async.cg.shared.global [%0], [%1], 16;"           \
                         :: "r"(dst_), "l"(src_) : "memory");                  \
        }                                                                      \
        asm volatile("cp.async.commit_group;" ::: "memory");                   \
    } while (0)

__global__ __launch_bounds__(256, 1) void attn_tc(
    const float* __restrict__ Qf,
    const __nv_bfloat16* __restrict__ Kh, const __nv_bfloat16* __restrict__ Kl,
    const __nv_bfloat16* __restrict__ Vh, const __nv_bfloat16* __restrict__ Vl,
    const int* __restrict__ cnt,
    __nv_bfloat16* __restrict__ OutH, __nv_bfloat16* __restrict__ OutL)
{
    extern __shared__ char smb[];
    const uint32_t sbase = smem_u32(smb);

    const int tid = threadIdx.x;
    const int lane = tid & 31;
    const int w = tid >> 5;
    const int b = blockIdx.z, h = blockIdx.y;
    const int q0 = blockIdx.x * 128;
    const int nlive = cnt[b];
    const size_t bh = (size_t)(b * HH + h) * SS;

    const float* Qb = Qf + (bh + q0) * HD;
#pragma unroll
    for (int it = 0; it < 8; it++) {
        int i = tid + it * 256;
        int row = i >> 4, c4 = (i & 15) * 4;
        float4 v = *(const float4*)(Qb + (size_t)row * HD + c4);
        uint32_t h0, h1, l0, l1;
        split4(v.x, v.y, v.z, v.w, h0, h1, l0, l1);
        uint32_t sw = SW128((uint32_t)(row * 128 + c4 * 2));
        *(uint2*)(smb + OFF_QH + sw) = make_uint2(h0, h1);
        *(uint2*)(smb + OFF_QL + sw) = make_uint2(l0, l1);
    }
    __syncthreads();

    uint32_t qh[4][4], ql[4][4];
    {
        const int grp = lane >> 3;
        const int arow = w * 16 + (grp & 1) * 8 + (lane & 7);
        const int adb = (grp >> 1) * 16;
#pragma unroll
        for (int kc = 0; kc < 4; kc++) {
            uint32_t sw = SW128((uint32_t)(arow * 128 + kc * 32 + adb));
            ldmatrix_x4(qh[kc][0], qh[kc][1], qh[kc][2], qh[kc][3], sbase + OFF_QH + sw);
            ldmatrix_x4(ql[kc][0], ql[kc][1], ql[kc][2], ql[kc][3], sbase + OFF_QL + sw);
        }
    }

    float Oacc[8][4];
#pragma unroll
    for (int i = 0; i < 8; i++)
#pragma unroll
        for (int j = 0; j < 4; j++) Oacc[i][j] = 0.f;
    float m0r = -1e30f, m1r = -1e30f, l0r = 0.f, l1r = 0.f;

    const int grp = lane >> 3;
    const int k_keyoff = (grp >> 1) * 8 + (lane & 7);
    const int k_dboff = (grp & 1) * 16;
    const int v_keyoff = (grp & 1) * 8 + (lane & 7);
    const int v_hdoff = (grp >> 1) * 16;

    const int ntile = (nlive + 63) >> 6;
    ISSUE_KV(0, 0);

    for (int t = 0; t < ntile; t++) {
        const int kt = t * 64;
        asm volatile("cp.async.wait_group 0;" ::: "memory");
        __syncthreads();
        if (t + 1 < ntile) ISSUE_KV(kt + 64, (t + 1) & 1);
        const uint32_t kvb = (uint32_t)(OFF_KV + (t & 1) * 32768);

        float sc[8][4];
#pragma unroll
        for (int i = 0; i < 8; i++)
#pragma unroll
            for (int j = 0; j < 4; j++) sc[i][j] = 0.f;

#pragma unroll
        for (int kc = 0; kc < 4; kc++) {
#pragma unroll
            for (int np = 0; np < 4; np++) {
                uint32_t swk = kvb + SW128((uint32_t)((np * 16 + k_keyoff) * 128 + kc * 32 + k_dboff));
                uint32_t kh0, kh1, kh2, kh3, kl0, kl1, kl2, kl3;
                ldmatrix_x4(kh0, kh1, kh2, kh3, sbase + swk);
                ldmatrix_x4(kl0, kl1, kl2, kl3, sbase + swk + 8192);
                mma_bf16(sc[2 * np], qh[kc][0], qh[kc][1], qh[kc][2], qh[kc][3], kh0, kh1);
                mma_bf16(sc[2 * np], qh[kc][0], qh[kc][1], qh[kc][2], qh[kc][3], kl0, kl1);
                mma_bf16(sc[2 * np], ql[kc][0], ql[kc][1], ql[kc][2], ql[kc][3], kh0, kh1);
                mma_bf16(sc[2 * np + 1], qh[kc][0], qh[kc][1], qh[kc][2], qh[kc][3], kh2, kh3);
                mma_bf16(sc[2 * np + 1], qh[kc][0], qh[kc][1], qh[kc][2], qh[kc][3], kl2, kl3);
                mma_bf16(sc[2 * np + 1], ql[kc][0], ql[kc][1], ql[kc][2], ql[kc][3], kh2, kh3);
            }
        }

        const bool tail = (kt + 64 > nlive);
        const int colbase = kt + (lane & 3) * 2;
#pragma unroll
        for (int i = 0; i < 8; i++) {
#pragma unroll
            for (int j = 0; j < 4; j++) sc[i][j] *= 0.125f;
        }
        if (tail) {
#pragma unroll
            for (int i = 0; i < 8; i++) {
                int c0 = colbase + i * 8;
                float bia0 = (c0 < nlive) ? 0.f : -1e9f;
                float bia1 = (c0 + 1 < nlive) ? 0.f : -1e9f;
                sc[i][0] += bia0; sc[i][1] += bia1;
                sc[i][2] += bia0; sc[i][3] += bia1;
            }
        }
        {
            float mx = sc[0][0];
#pragma unroll
            for (int i = 0; i < 8; i++) { mx = fmaxf(mx, sc[i][0]); mx = fmaxf(mx, sc[i][1]); }
            mx = fmaxf(mx, __shfl_xor_sync(0xffffffffu, mx, 1));
            mx = fmaxf(mx, __shfl_xor_sync(0xffffffffu, mx, 2));
            float nm = fmaxf(m0r, mx);
            float corr = __expf(m0r - nm);
            float ps = 0.f;
#pragma unroll
            for (int i = 0; i < 8; i++) {
                sc[i][0] = __expf(sc[i][0] - nm); ps += sc[i][0];
                sc[i][1] = __expf(sc[i][1] - nm); ps += sc[i][1];
            }
            ps += __shfl_xor_sync(0xffffffffu, ps, 1);
            ps += __shfl_xor_sync(0xffffffffu, ps, 2);
            l0r = l0r * corr + ps;
            m0r = nm;
#pragma unroll
            for (int i = 0; i < 8; i++) { Oacc[i][0] *= corr; Oacc[i][1] *= corr; }
        }
        {
            float mx = sc[0][2];
#pragma unroll
            for (int i = 0; i < 8; i++) { mx = fmaxf(mx, sc[i][2]); mx = fmaxf(mx, sc[i][3]); }
            mx = fmaxf(mx, __shfl_xor_sync(0xffffffffu, mx, 1));
            mx = fmaxf(mx, __shfl_xor_sync(0xffffffffu, mx, 2));
            float nm = fmaxf(m1r, mx);
            float corr = __expf(m1r - nm);
            float ps = 0.f;
#pragma unroll
            for (int i = 0; i < 8; i++) {
                sc[i][2] = __expf(sc[i][2] - nm); ps += sc[i][2];
                sc[i][3] = __expf(sc[i][3] - nm); ps += sc[i][3];
            }
            ps += __shfl_xor_sync(0xffffffffu, ps, 1);
            ps += __shfl_xor_sync(0xffffffffu, ps, 2);
            l1r = l1r * corr + ps;
            m1r = nm;
#pragma unroll
            for (int i = 0; i < 8; i++) { Oacc[i][2] *= corr; Oacc[i][3] *= corr; }
        }

#pragma unroll
        for (int kc = 0; kc < 4; kc++) {
            uint32_t ah0, ah1, ah2, ah3, al0, al1, al2, al3;
            split4(sc[2 * kc][0], sc[2 * kc][1], sc[2 * kc][2], sc[2 * kc][3],
                   ah0, ah1, al0, al1);
            split4(sc[2 * kc + 1][0], sc[2 * kc + 1][1], sc[2 * kc + 1][2], sc[2 * kc + 1][3],
                   ah2, ah3, al2, al3);
#pragma unroll
            for (int np = 0; np < 4; np++) {
                uint32_t swv = kvb + 16384u + SW128((uint32_t)((kc * 16 + v_keyoff) * 128 + np * 32 + v_hdoff));
                uint32_t vh0, vh1, vh2, vh3, vl0, vl1, vl2, vl3;
                ldmatrix_x4_trans(vh0, vh1, vh2, vh3, sbase + swv);
                ldmatrix_x4_trans(vl0, vl1, vl2, vl3, sbase + swv + 8192);
                mma_bf16(Oacc[2 * np], ah0, ah1, ah2, ah3, vh0, vh1);
                mma_bf16(Oacc[2 * np], ah0, ah1, ah2, ah3, vl0, vl1);
                mma_bf16(Oacc[2 * np], al0, al1, al2, al3, vh0, vh1);
                mma_bf16(Oacc[2 * np + 1], ah0, ah1, ah2, ah3, vh2, vh3);
                mma_bf16(Oacc[2 * np + 1], ah0, ah1, ah2, ah3, vl2, vl3);
                mma_bf16(Oacc[2 * np + 1], al0, al1, al2, al3, vh2, vh3);
            }
        }
    }

    // --- epilogue: write attn-out hi/lo bf16 planes ---
    const float inv0 = 1.0f / l0r;
    const float inv1 = 1.0f / l1r;
    const int rg0 = q0 + w * 16 + (lane >> 2);
    const int rg1 = rg0 + 8;
    const int cb = h * HD + (lane & 3) * 2;
#pragma unroll
    for (int nt = 0; nt < 8; nt++) {
        int col = cb + nt * 8;
        float v0 = Oacc[nt][0] * inv0, v1 = Oacc[nt][1] * inv0;
        uint32_t hi = pack2(v0, v1);
        float f0 = __uint_as_float(hi << 16), f1 = __uint_as_float(hi & 0xffff0000u);
        uint32_t lo = pack2(v0 - f0, v1 - f1);
        size_t ix0 = ((size_t)(b * SS + rg0)) * DD + col;
        *(uint32_t*)(OutH + ix0) = hi;
        *(uint32_t*)(OutL + ix0) = lo;
        v0 = Oacc[nt][2] * inv1; v1 = Oacc[nt][3] * inv1;
        hi = pack2(v0, v1);
        f0 = __uint_as_float(hi << 16); f1 = __uint_as_float(hi & 0xffff0000u);
        lo = pack2(v0 - f0, v1 - f1);
        size_t ix1 = ((size_t)(b * SS + rg1)) * DD + col;
        *(uint32_t*)(OutH + ix1) = hi;
        *(uint32_t*)(OutL + ix1) = lo;
    }
}

// ---------------------------------------------------------------------------
extern "C" void kernel_launch(void* const* d_in, const int* in_sizes, int n_in,
                              void* d_out, int out_size)
{
    const float* xq = (const float*)d_in[0];
    const float* xk = (const float*)d_in[1];
    const float* xv = (const float*)d_in[2];
    const int*   mask = (const int*)d_in[3];
    const float* wq = (const float*)d_in[4];
    const float* bq = (const float*)d_in[5];
    const float* wk = (const float*)d_in[6];
    const float* bk = (const float*)d_in[7];
    const float* wv = (const float*)d_in[8];
    const float* bv = (const float*)d_in[9];
    const float* wo = (const float*)d_in[10];
    const float* bo = (const float*)d_in[11];
    float* out = (float*)d_out;

    float* Qp;
    __nv_bfloat16 *Xhp, *Xlp, *Whp, *Wlp, *Khp, *Klp, *Vhp, *Vlp, *Ahp, *Alp;
    int *mapp, *cntp;
    cudaGetSymbolAddress((void**)&Qp, g_Q);
    cudaGetSymbolAddress((void**)&Xhp, g_Xh);
    cudaGetSymbolAddress((void**)&Xlp, g_Xl);
    cudaGetSymbolAddress((void**)&Whp, g_Wh);
    cudaGetSymbolAddress((void**)&Wlp, g_Wl);
    cudaGetSymbolAddress((void**)&Khp, g_Kh);
    cudaGetSymbolAddress((void**)&Klp, g_Kl);
    cudaGetSymbolAddress((void**)&Vhp, g_Vh);
    cudaGetSymbolAddress((void**)&Vlp, g_Vl);
    cudaGetSymbolAddress((void**)&Ahp, g_Ah);
    cudaGetSymbolAddress((void**)&Alp, g_Al);
    cudaGetSymbolAddress((void**)&mapp, g_map);
    cudaGetSymbolAddress((void**)&cntp, g_cnt);

    cudaFuncSetAttribute(attn_tc,
                         cudaFuncAttributeMaxDynamicSharedMemorySize, ATTN_SMEM);
    cudaFuncSetAttribute(tc_gemm_qkv,
                         cudaFuncAttributeMaxDynamicSharedMemorySize, GEMM_SMEM_P);
    cudaFuncSetAttribute(tc_gemm_out,
                         cudaFuncAttributeMaxDynamicSharedMemorySize, GEMM_SMEM_P);

    compact_idx<<<BB, 1024>>>(mask, mapp, cntp);
    cvt_x<<<dim3(MM * DD / 4 / 256, 1, 3), 256>>>(xq, xk, xv, Xhp, Xlp);
    cvt_w<<<dim3(DD * DD / 4 / 256, 1, 4), 256>>>(wq, wk, wv, wo, Whp, Wlp);

    tc_gemm_qkv<<<dim3(DD / 128, MM / 128, 3), 256, GEMM_SMEM_P>>>(
        Xhp, Xlp, Whp, Wlp, bq, bk, bv,
        Qp, Khp, Klp, Vhp, Vlp, mapp, cntp);

    attn_tc<<<dim3(SS / 128, HH, BB), 256, ATTN_SMEM>>>(
        Qp, Khp, Klp, Vhp, Vlp, cntp, Ahp, Alp);

    tc_gemm_out<<<dim3(DD / 128, MM / 128), 256, GEMM_SMEM_P>>>(
        Ahp, Alp, Whp, Wlp, bo, out);
}

// round 12
// speedup vs baseline: 5.0076x; 1.0006x over previous
#include <cuda_runtime.h>
#include <cuda_bf16.h>
#include <cstdint>

#define BB 2
#define SS 2048
#define DD 1024
#define HH 16
#define HD 64
#define MM (BB * SS)   // 4096 rows

// Scratch (allocation-free rule: __device__ globals)
__device__ __align__(16) float g_Q[MM * DD];                  // (B,H,S,HD) fp32
__device__ __align__(16) __nv_bfloat16 g_Xh[3 * MM * DD];     // xq,xk,xv hi
__device__ __align__(16) __nv_bfloat16 g_Xl[3 * MM * DD];     // xq,xk,xv lo
__device__ __align__(16) __nv_bfloat16 g_Wh[4 * DD * DD];     // wq,wk,wv,wo hi
__device__ __align__(16) __nv_bfloat16 g_Wl[4 * DD * DD];     // wq,wk,wv,wo lo
__device__ __align__(16) __nv_bfloat16 g_Kh[MM * DD];         // compacted K hi
__device__ __align__(16) __nv_bfloat16 g_Kl[MM * DD];
__device__ __align__(16) __nv_bfloat16 g_Vh[MM * DD];
__device__ __align__(16) __nv_bfloat16 g_Vl[MM * DD];
__device__ __align__(16) __nv_bfloat16 g_Ah[MM * DD];         // attn out hi (B,S,D)
__device__ __align__(16) __nv_bfloat16 g_Al[MM * DD];         // attn out lo
__device__ int g_map[BB * SS];
__device__ int g_cnt[BB];

// ===========================================================================
// helpers
// ===========================================================================
__device__ __forceinline__ uint32_t smem_u32(const void* p) {
    uint32_t a;
    asm("{ .reg .u64 t; cvta.to.shared.u64 t, %1; cvt.u32.u64 %0, t; }"
        : "=r"(a) : "l"(p));
    return a;
}

__device__ __forceinline__ void ldmatrix_x4(uint32_t& r0, uint32_t& r1,
                                            uint32_t& r2, uint32_t& r3,
                                            uint32_t addr) {
    asm volatile("ldmatrix.sync.aligned.m8n8.x4.shared.b16 {%0,%1,%2,%3}, [%4];"
                 : "=r"(r0), "=r"(r1), "=r"(r2), "=r"(r3) : "r"(addr));
}

__device__ __forceinline__ void ldmatrix_x4_trans(uint32_t& r0, uint32_t& r1,
                                                  uint32_t& r2, uint32_t& r3,
                                                  uint32_t addr) {
    asm volatile("ldmatrix.sync.aligned.m8n8.x4.trans.shared.b16 {%0,%1,%2,%3}, [%4];"
                 : "=r"(r0), "=r"(r1), "=r"(r2), "=r"(r3) : "r"(addr));
}

__device__ __forceinline__ void mma_bf16(float* d,
                                         uint32_t a0, uint32_t a1, uint32_t a2, uint32_t a3,
                                         uint32_t b0, uint32_t b1) {
    asm volatile(
        "mma.sync.aligned.m16n8k16.row.col.f32.bf16.bf16.f32 "
        "{%0,%1,%2,%3}, {%4,%5,%6,%7}, {%8,%9}, {%0,%1,%2,%3};"
        : "+f"(d[0]), "+f"(d[1]), "+f"(d[2]), "+f"(d[3])
        : "r"(a0), "r"(a1), "r"(a2), "r"(a3), "r"(b0), "r"(b1));
}

__device__ __forceinline__ uint32_t pack2(float x, float y) {
    __nv_bfloat162 h = __floats2bfloat162_rn(x, y);
    return *reinterpret_cast<uint32_t*>(&h);
}

__device__ __forceinline__ void split4(float x, float y, float z, float w,
                                       uint32_t& h0, uint32_t& h1,
                                       uint32_t& l0, uint32_t& l1) {
    h0 = pack2(x, y); h1 = pack2(z, w);
    float fx = __uint_as_float(h0 << 16), fy = __uint_as_float(h0 & 0xffff0000u);
    float fz = __uint_as_float(h1 << 16), fw = __uint_as_float(h1 & 0xffff0000u);
    l0 = pack2(x - fx, y - fy); l1 = pack2(z - fz, w - fw);
}

#define SW128(o) ((o) ^ (((o) >> 3) & 0x70))

// ===========================================================================
// Conversion kernels: fp32 -> bf16 hi/lo planes
// ===========================================================================
__global__ __launch_bounds__(256) void cvt_x(
    const float* __restrict__ x0, const float* __restrict__ x1,
    const float* __restrict__ x2,
    __nv_bfloat16* __restrict__ H, __nv_bfloat16* __restrict__ L)
{
    const float* src = (blockIdx.z == 0) ? x0 : (blockIdx.z == 1) ? x1 : x2;
    const size_t base = (size_t)blockIdx.z * MM * DD;
    const size_t i = (size_t)blockIdx.x * 256 + threadIdx.x;   // float4 idx
    float4 v = *((const float4*)src + i);
    uint32_t h0, h1, l0, l1;
    split4(v.x, v.y, v.z, v.w, h0, h1, l0, l1);
    *(uint2*)(H + base + i * 4) = make_uint2(h0, h1);
    *(uint2*)(L + base + i * 4) = make_uint2(l0, l1);
}

__global__ __launch_bounds__(256) void cvt_w(
    const float* __restrict__ w0, const float* __restrict__ w1,
    const float* __restrict__ w2, const float* __restrict__ w3,
    __nv_bfloat16* __restrict__ H, __nv_bfloat16* __restrict__ L)
{
    const float* src = (blockIdx.z == 0) ? w0 : (blockIdx.z == 1) ? w1
                       : (blockIdx.z == 2) ? w2 : w3;
    const size_t base = (size_t)blockIdx.z * DD * DD;
    const size_t i = (size_t)blockIdx.x * 256 + threadIdx.x;
    float4 v = *((const float4*)src + i);
    uint32_t h0, h1, l0, l1;
    split4(v.x, v.y, v.z, v.w, h0, h1, l0, l1);
    *(uint2*)(H + base + i * 4) = make_uint2(h0, h1);
    *(uint2*)(L + base + i * 4) = make_uint2(l0, l1);
}

// ===========================================================================
// Pipelined bf16x3 GEMM: 128x128 tile, K-chunk 16, 6-stage cp.async,
// register double-buffered ldmatrix fragments (1 CTA/SM).
// ===========================================================================
#define ASTR 24
#define PLANE_B (128 * ASTR * 2)       // 6144
#define CHUNK_B (4 * PLANE_B)          // 24576
#define PIPE_S 6
#define GEMM_SMEM_P (PIPE_S * CHUNK_B) // 147456

#define GEMM_VARS()                                                            \
    extern __shared__ char smc[];                                              \
    const uint32_t sb = smem_u32(smc);                                         \
    const int tid = threadIdx.x;                                               \
    const int lane = tid & 31;                                                 \
    const int wid = tid >> 5;                                                  \
    const int warp_m = wid & 1;                                                \
    const int warp_n = wid >> 1;                                               \
    const int bm = blockIdx.y * 128;                                           \
    const int bn = blockIdx.x * 128;                                           \
    const int r = tid >> 1;                                                    \
    const int hf = tid & 1;                                                    \
    const uint32_t st16 = (uint32_t)(r * 48 + hf * 16);                        \
    const uint32_t aoff = (uint32_t)((warp_m * 64 + (lane & 15)) * 48 + (lane >> 4) * 16); \
    const uint32_t boff = (uint32_t)((warp_n * 32 + (lane & 15)) * 48 + (lane >> 4) * 16);

#define ISSUE_CHUNK(cc, stg)                                                   \
    do {                                                                       \
        uint32_t dst_ = sb + (uint32_t)(stg) * CHUNK_B + st16;                 \
        const char* s0_ = pAh + (size_t)(cc) * 32;                             \
        const char* s1_ = pAl + (size_t)(cc) * 32;                             \
        const char* s2_ = pBh + (size_t)(cc) * 32;                             \
        const char* s3_ = pBl + (size_t)(cc) * 32;                             \
        asm volatile("cp.async.cg.shared.global [%0], [%1], 16, %2;"           \
                     :: "r"(dst_), "l"(s0_), "r"(asz) : "memory");             \
        asm volatile("cp.async.cg.shared.global [%0], [%1], 16, %2;"           \
                     :: "r"(dst_ + PLANE_B), "l"(s1_), "r"(asz) : "memory");   \
        asm volatile("cp.async.cg.shared.global [%0], [%1], 16;"               \
                     :: "r"(dst_ + 2 * PLANE_B), "l"(s2_) : "memory");         \
        asm volatile("cp.async.cg.shared.global [%0], [%1], 16;"               \
                     :: "r"(dst_ + 3 * PLANE_B), "l"(s3_) : "memory");         \
        asm volatile("cp.async.commit_group;" ::: "memory");                   \
    } while (0)

// load fragments for one chunk from stage base into named frag arrays
#define LOADFRAG(FA_h, FA_l, FB_h, FB_l, base_)                                \
    do {                                                                       \
        _Pragma("unroll") for (int p = 0; p < 2; p++) {                        \
            uint32_t t0, t1, t2, t3;                                           \
            ldmatrix_x4(t0, t1, t2, t3, (base_) + 2 * PLANE_B + boff + p * 768u); \
            FB_h[p * 2][0] = t0;     FB_h[p * 2][1] = t2;                      \
            FB_h[p * 2 + 1][0] = t1; FB_h[p * 2 + 1][1] = t3;                  \
            ldmatrix_x4(t0, t1, t2, t3, (base_) + 3 * PLANE_B + boff + p * 768u); \
            FB_l[p * 2][0] = t0;     FB_l[p * 2][1] = t2;                      \
            FB_l[p * 2 + 1][0] = t1; FB_l[p * 2 + 1][1] = t3;                  \
        }                                                                      \
        _Pragma("unroll") for (int mi = 0; mi < 4; mi++) {                     \
            ldmatrix_x4(FA_h[mi][0], FA_h[mi][1], FA_h[mi][2], FA_h[mi][3],    \
                        (base_) + aoff + mi * 768u);                           \
            ldmatrix_x4(FA_l[mi][0], FA_l[mi][1], FA_l[mi][2], FA_l[mi][3],    \
                        (base_) + PLANE_B + aoff + mi * 768u);                 \
        }                                                                      \
    } while (0)

#define COMPUTE_FRAG(FA_h, FA_l, FB_h, FB_l)                                   \
    do {                                                                       \
        _Pragma("unroll") for (int mi = 0; mi < 4; mi++)                       \
            _Pragma("unroll") for (int ni = 0; ni < 4; ni++) {                 \
                float* d = acc[mi][ni];                                        \
                mma_bf16(d, FA_h[mi][0], FA_h[mi][1], FA_h[mi][2], FA_h[mi][3],\
                         FB_h[ni][0], FB_h[ni][1]);                            \
                mma_bf16(d, FA_h[mi][0], FA_h[mi][1], FA_h[mi][2], FA_h[mi][3],\
                         FB_l[ni][0], FB_l[ni][1]);                            \
                mma_bf16(d, FA_l[mi][0], FA_l[mi][1], FA_l[mi][2], FA_l[mi][3],\
                         FB_h[ni][0], FB_h[ni][1]);                            \
            }                                                                  \
    } while (0)

#define WAITG(c_)                                                              \
    do {                                                                       \
        if ((c_) < 60)      asm volatile("cp.async.wait_group 3;" ::: "memory"); \
        else if ((c_) == 60) asm volatile("cp.async.wait_group 2;" ::: "memory"); \
        else if ((c_) == 61) asm volatile("cp.async.wait_group 1;" ::: "memory"); \
        else                 asm volatile("cp.async.wait_group 0;" ::: "memory"); \
    } while (0)

// One mainloop step: cur frags hold chunk c; prefetch frags for c+1.
#define STEP(c_, CAh, CAl, CBh, CBl, NAh, NAl, NBh, NBl)                       \
    do {                                                                       \
        if ((c_) + 5 < 64) ISSUE_CHUNK((c_) + 5, ((c_) + 5) % PIPE_S);         \
        WAITG(c_);                                                             \
        __syncthreads();                                                       \
        if ((c_) + 1 < 64)                                                     \
            LOADFRAG(NAh, NAl, NBh, NBl, sb + (uint32_t)((((c_) + 1) % PIPE_S)) * CHUNK_B); \
        COMPUTE_FRAG(CAh, CAl, CBh, CBl);                                      \
    } while (0)

#define PIPE_MAINLOOP()                                                        \
    uint32_t Aah[4][4], Aal[4][4], Abh[4][2], Abl[4][2];                       \
    uint32_t Bah[4][4], Bal[4][4], Bbh[4][2], Bbl[4][2];                       \
    ISSUE_CHUNK(0, 0); ISSUE_CHUNK(1, 1); ISSUE_CHUNK(2, 2);                   \
    ISSUE_CHUNK(3, 3); ISSUE_CHUNK(4, 4);                                      \
    asm volatile("cp.async.wait_group 3;" ::: "memory");                       \
    __syncthreads();                                                           \
    LOADFRAG(Aah, Aal, Abh, Abl, sb);                                          \
    for (int c = 0; c < 64; c += 2) {                                          \
        STEP(c,     Aah, Aal, Abh, Abl, Bah, Bal, Bbh, Bbl);                   \
        STEP(c + 1, Bah, Bal, Bbh, Bbl, Aah, Aal, Abh, Abl);                   \
    }

// ===========================================================================
// Merged QKV projection GEMM (bf16-plane inputs).
// z: 0 -> Q (fp32 head-split out), 1 -> K, 2 -> V (compacted bf16 planes).
// ===========================================================================
__global__ __launch_bounds__(256) void tc_gemm_qkv(
    const __nv_bfloat16* __restrict__ Xh, const __nv_bfloat16* __restrict__ Xl,
    const __nv_bfloat16* __restrict__ Wh, const __nv_bfloat16* __restrict__ Wl,
    const float* __restrict__ bq, const float* __restrict__ bk,
    const float* __restrict__ bv,
    float* __restrict__ Qout,
    __nv_bfloat16* __restrict__ Kh, __nv_bfloat16* __restrict__ Kl,
    __nv_bfloat16* __restrict__ Vh, __nv_bfloat16* __restrict__ Vl,
    const int* __restrict__ rowmap, const int* __restrict__ cnt)
{
    const int z = blockIdx.z;
    GEMM_VARS();

    const int batch = bm >> 11;
    int nlive = SS;
    if (z > 0) {
        nlive = cnt[batch];
        if ((bm & (SS - 1)) >= ((nlive + 127) & ~127)) return;   // dead tile
    }

    uint32_t asz = 16;
    int gr;
    if (z == 0) {
        gr = bm + r;
    } else {
        int g = rowmap[bm + r];
        asz = (g >= 0) ? 16u : 0u;
        gr = (g >= 0) ? g : 0;
    }
    const __nv_bfloat16* Xph = Xh + (size_t)z * MM * DD;
    const __nv_bfloat16* Xpl = Xl + (size_t)z * MM * DD;
    const __nv_bfloat16* Wph = Wh + (size_t)z * DD * DD;
    const __nv_bfloat16* Wpl = Wl + (size_t)z * DD * DD;
    const float* bias = (z == 0) ? bq : (z == 1) ? bk : bv;

    const char* pAh = (const char*)(Xph + (size_t)gr * DD) + hf * 16;
    const char* pAl = (const char*)(Xpl + (size_t)gr * DD) + hf * 16;
    const char* pBh = (const char*)(Wph + (size_t)(bn + r) * DD) + hf * 16;
    const char* pBl = (const char*)(Wpl + (size_t)(bn + r) * DD) + hf * 16;

    float acc[4][4][4];
#pragma unroll
    for (int i = 0; i < 4; i++)
#pragma unroll
        for (int j = 0; j < 4; j++)
#pragma unroll
            for (int k = 0; k < 4; k++) acc[i][j][k] = 0.f;

    PIPE_MAINLOOP();

    // ---- epilogue ----
    __nv_bfloat16* Ph = (z == 1) ? Kh : Vh;
    __nv_bfloat16* Pl = (z == 1) ? Kl : Vl;
#pragma unroll
    for (int mi = 0; mi < 4; mi++) {
#pragma unroll
        for (int ni = 0; ni < 4; ni++) {
            int m0 = bm + warp_m * 64 + mi * 16 + (lane >> 2);
            int n = bn + warp_n * 32 + ni * 8 + (lane & 3) * 2;
            float b0v = bias[n], b1v = bias[n + 1];
#pragma unroll
            for (int half = 0; half < 2; half++) {
                int m = m0 + half * 8;
                float v0 = acc[mi][ni][half * 2 + 0];
                float v1 = acc[mi][ni][half * 2 + 1];
                int s = m & (SS - 1);
                int hh = n >> 6;
                int hd = n & (HD - 1);
                if (z == 0) {
                    float2 v = make_float2(v0 + b0v, v1 + b1v);
                    *(float2*)(Qout + (((size_t)(batch * HH + hh)) * SS + s) * HD + hd) = v;
                } else {
                    if (s < nlive) { v0 += b0v; v1 += b1v; }
                    else           { v0 = 0.f;  v1 = 0.f; }
                    uint32_t hi = pack2(v0, v1);
                    float f0 = __uint_as_float(hi << 16);
                    float f1 = __uint_as_float(hi & 0xffff0000u);
                    uint32_t lo = pack2(v0 - f0, v1 - f1);
                    size_t basei = (((size_t)(batch * HH + hh)) * SS + s) * HD + hd;
                    *(uint32_t*)(Ph + basei) = hi;
                    *(uint32_t*)(Pl + basei) = lo;
                }
            }
        }
    }
}

// ===========================================================================
// Output GEMM: A = attn-out planes, W = wo planes, fp32 out.
// ===========================================================================
__global__ __launch_bounds__(256) void tc_gemm_out(
    const __nv_bfloat16* __restrict__ Ah, const __nv_bfloat16* __restrict__ Al,
    const __nv_bfloat16* __restrict__ Wh, const __nv_bfloat16* __restrict__ Wl,
    const float* __restrict__ bias, float* __restrict__ C)
{
    GEMM_VARS();
    const uint32_t asz = 16;
    const char* pAh = (const char*)(Ah + (size_t)(bm + r) * DD) + hf * 16;
    const char* pAl = (const char*)(Al + (size_t)(bm + r) * DD) + hf * 16;
    const char* pBh = (const char*)(Wh + (size_t)(3 * DD * DD) + (size_t)(bn + r) * DD) + hf * 16;
    const char* pBl = (const char*)(Wl + (size_t)(3 * DD * DD) + (size_t)(bn + r) * DD) + hf * 16;

    float acc[4][4][4];
#pragma unroll
    for (int i = 0; i < 4; i++)
#pragma unroll
        for (int j = 0; j < 4; j++)
#pragma unroll
            for (int k = 0; k < 4; k++) acc[i][j][k] = 0.f;

    PIPE_MAINLOOP();

#pragma unroll
    for (int mi = 0; mi < 4; mi++) {
#pragma unroll
        for (int ni = 0; ni < 4; ni++) {
            int m0 = bm + warp_m * 64 + mi * 16 + (lane >> 2);
            int n = bn + warp_n * 32 + ni * 8 + (lane & 3) * 2;
            float b0v = bias[n], b1v = bias[n + 1];
#pragma unroll
            for (int half = 0; half < 2; half++) {
                int m = m0 + half * 8;
                float2 v;
                v.x = acc[mi][ni][half * 2 + 0] + b0v;
                v.y = acc[mi][ni][half * 2 + 1] + b1v;
                *(float2*)(C + (size_t)m * DD + n) = v;
            }
        }
    }
}

// ===========================================================================
// Mask compaction (unchanged)
// ===========================================================================
__global__ __launch_bounds__(1024) void compact_idx(
    const int* __restrict__ mask, int* __restrict__ rowmap, int* __restrict__ cnt)
{
    const int b = blockIdx.x;
    __shared__ int wsum[32];
    const int t = threadIdx.x;
    const int lane = t & 31;
    const int w = t >> 5;

    const int p0 = 2 * t, p1 = 2 * t + 1;
    const int m0 = mask[b * SS + p0] != 0;
    const int m1 = mask[b * SS + p1] != 0;
    const int local = m0 + m1;

    rowmap[b * SS + p0] = -1;
    rowmap[b * SS + p1] = -1;

    int v = local;
#pragma unroll
    for (int off = 1; off < 32; off <<= 1) {
        int u = __shfl_up_sync(0xffffffffu, v, off);
        if (lane >= off) v += u;
    }
    if (lane == 31) wsum[w] = v;
    __syncthreads();
    if (w == 0) {
        int s = wsum[lane];
#pragma unroll
        for (int off = 1; off < 32; off <<= 1) {
            int u = __shfl_up_sync(0xffffffffu, s, off);
            if (lane >= off) s += u;
        }
        wsum[lane] = s;
    }
    __syncthreads();

    const int base = (w > 0 ? wsum[w - 1] : 0) + (v - local);
    if (m0) rowmap[b * SS + base] = b * SS + p0;
    if (m1) rowmap[b * SS + base + m0] = b * SS + p1;
    if (t == 1023) cnt[b] = wsum[31];
}

// ===========================================================================
// Tensor-core flash attention, 2-stage cp.async K/V pipeline (unchanged).
// ===========================================================================
#define OFF_QH 0
#define OFF_QL 16384
#define OFF_KV 32768
#define ATTN_SMEM (32768 + 2 * 32768)   // 98304

#define ISSUE_KV(ktv, stg)                                                     \
    do {                                                                       \
        _Pragma("unroll") for (int it = 0; it < 8; it++) {                     \
            int i_ = tid + it * 256;                                           \
            int plane_ = i_ >> 9;                                              \
            int idx_ = i_ & 511;                                               \
            int row_ = idx_ >> 3, ch_ = idx_ & 7;                              \
            const __nv_bfloat16* sp_ =                                         \
                (plane_ == 0) ? Kh : (plane_ == 1) ? Kl : (plane_ == 2) ? Vh : Vl; \
            const char* src_ = (const char*)(sp_ + (bh + (ktv) + row_) * HD) + ch_ * 16; \
            uint32_t dst_ = sbase + (uint32_t)(OFF_KV + (stg) * 32768 + plane_ * 8192 \
                            + SW128((uint32_t)(row_ * 128 + ch_ * 16)));       \
            asm volatile("cp.async.cg.shared.global [%0], [%1], 16;"           \
                         :: "r"(dst_), "l"(src_) : "memory");                  \
        }                                                                      \
        asm volatile("cp.async.commit_group;" ::: "memory");                   \
    } while (0)

__global__ __launch_bounds__(256, 1) void attn_tc(
    const float* __restrict__ Qf,
    const __nv_bfloat16* __restrict__ Kh, const __nv_bfloat16* __restrict__ Kl,
    const __nv_bfloat16* __restrict__ Vh, const __nv_bfloat16* __restrict__ Vl,
    const int* __restrict__ cnt,
    __nv_bfloat16* __restrict__ OutH, __nv_bfloat16* __restrict__ OutL)
{
    extern __shared__ char smb[];
    const uint32_t sbase = smem_u32(smb);

    const int tid = threadIdx.x;
    const int lane = tid & 31;
    const int w = tid >> 5;
    const int b = blockIdx.z, h = blockIdx.y;
    const int q0 = blockIdx.x * 128;
    const int nlive = cnt[b];
    const size_t bh = (size_t)(b * HH + h) * SS;

    const float* Qb = Qf + (bh + q0) * HD;
#pragma unroll
    for (int it = 0; it < 8; it++) {
        int i = tid + it * 256;
        int row = i >> 4, c4 = (i & 15) * 4;
        float4 v = *(const float4*)(Qb + (size_t)row * HD + c4);
        uint32_t h0, h1, l0, l1;
        split4(v.x, v.y, v.z, v.w, h0, h1, l0, l1);
        uint32_t sw = SW128((uint32_t)(row * 128 + c4 * 2));
        *(uint2*)(smb + OFF_QH + sw) = make_uint2(h0, h1);
        *(uint2*)(smb + OFF_QL + sw) = make_uint2(l0, l1);
    }
    __syncthreads();

    uint32_t qh[4][4], ql[4][4];
    {
        const int grp = lane >> 3;
        const int arow = w * 16 + (grp & 1) * 8 + (lane & 7);
        const int adb = (grp >> 1) * 16;
#pragma unroll
        for (int kc = 0; kc < 4; kc++) {
            uint32_t sw = SW128((uint32_t)(arow * 128 + kc * 32 + adb));
            ldmatrix_x4(qh[kc][0], qh[kc][1], qh[kc][2], qh[kc][3], sbase + OFF_QH + sw);
            ldmatrix_x4(ql[kc][0], ql[kc][1], ql[kc][2], ql[kc][3], sbase + OFF_QL + sw);
        }
    }

    float Oacc[8][4];
#pragma unroll
    for (int i = 0; i < 8; i++)
#pragma unroll
        for (int j = 0; j < 4; j++) Oacc[i][j] = 0.f;
    float m0r = -1e30f, m1r = -1e30f, l0r = 0.f, l1r = 0.f;

    const int grp = lane >> 3;
    const int k_keyoff = (grp >> 1) * 8 + (lane & 7);
    const int k_dboff = (grp & 1) * 16;
    const int v_keyoff = (grp & 1) * 8 + (lane & 7);
    const int v_hdoff = (grp >> 1) * 16;

    const int ntile = (nlive + 63) >> 6;
    ISSUE_KV(0, 0);

    for (int t = 0; t < ntile; t++) {
        const int kt = t * 64;
        asm volatile("cp.async.wait_group 0;" ::: "memory");
        __syncthreads();
        if (t + 1 < ntile) ISSUE_KV(kt + 64, (t + 1) & 1);
        const uint32_t kvb = (uint32_t)(OFF_KV + (t & 1) * 32768);

        float sc[8][4];
#pragma unroll
        for (int i = 0; i < 8; i++)
#pragma unroll
            for (int j = 0; j < 4; j++) sc[i][j] = 0.f;

#pragma unroll
        for (int kc = 0; kc < 4; kc++) {
#pragma unroll
            for (int np = 0; np < 4; np++) {
                uint32_t swk = kvb + SW128((uint32_t)((np * 16 + k_keyoff) * 128 + kc * 32 + k_dboff));
                uint32_t kh0, kh1, kh2, kh3, kl0, kl1, kl2, kl3;
                ldmatrix_x4(kh0, kh1, kh2, kh3, sbase + swk);
                ldmatrix_x4(kl0, kl1, kl2, kl3, sbase + swk + 8192);
                mma_bf16(sc[2 * np], qh[kc][0], qh[kc][1], qh[kc][2], qh[kc][3], kh0, kh1);
                mma_bf16(sc[2 * np], qh[kc][0], qh[kc][1], qh[kc][2], qh[kc][3], kl0, kl1);
                mma_bf16(sc[2 * np], ql[kc][0], ql[kc][1], ql[kc][2], ql[kc][3], kh0, kh1);
                mma_bf16(sc[2 * np + 1], qh[kc][0], qh[kc][1], qh[kc][2], qh[kc][3], kh2, kh3);
                mma_bf16(sc[2 * np + 1], qh[kc][0], qh[kc][1], qh[kc][2], qh[kc][3], kl2, kl3);
                mma_bf16(sc[2 * np + 1], ql[kc][0], ql[kc][1], ql[kc][2], ql[kc][3], kh2, kh3);
            }
        }

        const bool tail = (kt + 64 > nlive);
        const int colbase = kt + (lane & 3) * 2;
#pragma unroll
        for (int i = 0; i < 8; i++) {
#pragma unroll
            for (int j = 0; j < 4; j++) sc[i][j] *= 0.125f;
        }
        if (tail) {
#pragma unroll
            for (int i = 0; i < 8; i++) {
                int c0 = colbase + i * 8;
                float bia0 = (c0 < nlive) ? 0.f : -1e9f;
                float bia1 = (c0 + 1 < nlive) ? 0.f : -1e9f;
                sc[i][0] += bia0; sc[i][1] += bia1;
                sc[i][2] += bia0; sc[i][3] += bia1;
            }
        }
        {
            float mx = sc[0][0];
#pragma unroll
            for (int i = 0; i < 8; i++) { mx = fmaxf(mx, sc[i][0]); mx = fmaxf(mx, sc[i][1]); }
            mx = fmaxf(mx, __shfl_xor_sync(0xffffffffu, mx, 1));
            mx = fmaxf(mx, __shfl_xor_sync(0xffffffffu, mx, 2));
            float nm = fmaxf(m0r, mx);
            float corr = __expf(m0r - nm);
            float ps = 0.f;
#pragma unroll
            for (int i = 0; i < 8; i++) {
                sc[i][0] = __expf(sc[i][0] - nm); ps += sc[i][0];
                sc[i][1] = __expf(sc[i][1] - nm); ps += sc[i][1];
            }
            ps += __shfl_xor_sync(0xffffffffu, ps, 1);
            ps += __shfl_xor_sync(0xffffffffu, ps, 2);
            l0r = l0r * corr + ps;
            m0r = nm;
#pragma unroll
            for (int i = 0; i < 8; i++) { Oacc[i][0] *= corr; Oacc[i][1] *= corr; }
        }
        {
            float mx = sc[0][2];
#pragma unroll
            for (int i = 0; i < 8; i++) { mx = fmaxf(mx, sc[i][2]); mx = fmaxf(mx, sc[i][3]); }
            mx = fmaxf(mx, __shfl_xor_sync(0xffffffffu, mx, 1));
            mx = fmaxf(mx, __shfl_xor_sync(0xffffffffu, mx, 2));
            float nm = fmaxf(m1r, mx);
            float corr = __expf(m1r - nm);
            float ps = 0.f;
#pragma unroll
            for (int i = 0; i < 8; i++) {
                sc[i][2] = __expf(sc[i][2] - nm); ps += sc[i][2];
                sc[i][3] = __expf(sc[i][3] - nm); ps += sc[i][3];
            }
            ps += __shfl_xor_sync(0xffffffffu, ps, 1);
            ps += __shfl_xor_sync(0xffffffffu, ps, 2);
            l1r = l1r * corr + ps;
            m1r = nm;
#pragma unroll
            for (int i = 0; i < 8; i++) { Oacc[i][2] *= corr; Oacc[i][3] *= corr; }
        }

#pragma unroll
        for (int kc = 0; kc < 4; kc++) {
            uint32_t ah0, ah1, ah2, ah3, al0, al1, al2, al3;
            split4(sc[2 * kc][0], sc[2 * kc][1], sc[2 * kc][2], sc[2 * kc][3],
                   ah0, ah1, al0, al1);
            split4(sc[2 * kc + 1][0], sc[2 * kc + 1][1], sc[2 * kc + 1][2], sc[2 * kc + 1][3],
                   ah2, ah3, al2, al3);
#pragma unroll
            for (int np = 0; np < 4; np++) {
                uint32_t swv = kvb + 16384u + SW128((uint32_t)((kc * 16 + v_keyoff) * 128 + np * 32 + v_hdoff));
                uint32_t vh0, vh1, vh2, vh3, vl0, vl1, vl2, vl3;
                ldmatrix_x4_trans(vh0, vh1, vh2, vh3, sbase + swv);
                ldmatrix_x4_trans(vl0, vl1, vl2, vl3, sbase + swv + 8192);
                mma_bf16(Oacc[2 * np], ah0, ah1, ah2, ah3, vh0, vh1);
                mma_bf16(Oacc[2 * np], ah0, ah1, ah2, ah3, vl0, vl1);
                mma_bf16(Oacc[2 * np], al0, al1, al2, al3, vh0, vh1);
                mma_bf16(Oacc[2 * np + 1], ah0, ah1, ah2, ah3, vh2, vh3);
                mma_bf16(Oacc[2 * np + 1], ah0, ah1, ah2, ah3, vl2, vl3);
                mma_bf16(Oacc[2 * np + 1], al0, al1, al2, al3, vh2, vh3);
            }
        }
    }

    // --- epilogue: write attn-out hi/lo bf16 planes ---
    const float inv0 = 1.0f / l0r;
    const float inv1 = 1.0f / l1r;
    const int rg0 = q0 + w * 16 + (lane >> 2);
    const int rg1 = rg0 + 8;
    const int cb = h * HD + (lane & 3) * 2;
#pragma unroll
    for (int nt = 0; nt < 8; nt++) {
        int col = cb + nt * 8;
        float v0 = Oacc[nt][0] * inv0, v1 = Oacc[nt][1] * inv0;
        uint32_t hi = pack2(v0, v1);
        float f0 = __uint_as_float(hi << 16), f1 = __uint_as_float(hi & 0xffff0000u);
        uint32_t lo = pack2(v0 - f0, v1 - f1);
        size_t ix0 = ((size_t)(b * SS + rg0)) * DD + col;
        *(uint32_t*)(OutH + ix0) = hi;
        *(uint32_t*)(OutL + ix0) = lo;
        v0 = Oacc[nt][2] * inv1; v1 = Oacc[nt][3] * inv1;
        hi = pack2(v0, v1);
        f0 = __uint_as_float(hi << 16); f1 = __uint_as_float(hi & 0xffff0000u);
        lo = pack2(v0 - f0, v1 - f1);
        size_t ix1 = ((size_t)(b * SS + rg1)) * DD + col;
        *(uint32_t*)(OutH + ix1) = hi;
        *(uint32_t*)(OutL + ix1) = lo;
    }
}

// ---------------------------------------------------------------------------
extern "C" void kernel_launch(void* const* d_in, const int* in_sizes, int n_in,
                              void* d_out, int out_size)
{
    const float* xq = (const float*)d_in[0];
    const float* xk = (const float*)d_in[1];
    const float* xv = (const float*)d_in[2];
    const int*   mask = (const int*)d_in[3];
    const float* wq = (const float*)d_in[4];
    const float* bq = (const float*)d_in[5];
    const float* wk = (const float*)d_in[6];
    const float* bk = (const float*)d_in[7];
    const float* wv = (const float*)d_in[8];
    const float* bv = (const float*)d_in[9];
    const float* wo = (const float*)d_in[10];
    const float* bo = (const float*)d_in[11];
    float* out = (float*)d_out;

    float* Qp;
    __nv_bfloat16 *Xhp, *Xlp, *Whp, *Wlp, *Khp, *Klp, *Vhp, *Vlp, *Ahp, *Alp;
    int *mapp, *cntp;
    cudaGetSymbolAddress((void**)&Qp, g_Q);
    cudaGetSymbolAddress((void**)&Xhp, g_Xh);
    cudaGetSymbolAddress((void**)&Xlp, g_Xl);
    cudaGetSymbolAddress((void**)&Whp, g_Wh);
    cudaGetSymbolAddress((void**)&Wlp, g_Wl);
    cudaGetSymbolAddress((void**)&Khp, g_Kh);
    cudaGetSymbolAddress((void**)&Klp, g_Kl);
    cudaGetSymbolAddress((void**)&Vhp, g_Vh);
    cudaGetSymbolAddress((void**)&Vlp, g_Vl);
    cudaGetSymbolAddress((void**)&Ahp, g_Ah);
    cudaGetSymbolAddress((void**)&Alp, g_Al);
    cudaGetSymbolAddress((void**)&mapp, g_map);
    cudaGetSymbolAddress((void**)&cntp, g_cnt);

    cudaFuncSetAttribute(attn_tc,
                         cudaFuncAttributeMaxDynamicSharedMemorySize, ATTN_SMEM);
    cudaFuncSetAttribute(tc_gemm_qkv,
                         cudaFuncAttributeMaxDynamicSharedMemorySize, GEMM_SMEM_P);
    cudaFuncSetAttribute(tc_gemm_out,
                         cudaFuncAttributeMaxDynamicSharedMemorySize, GEMM_SMEM_P);

    compact_idx<<<BB, 1024>>>(mask, mapp, cntp);
    cvt_x<<<dim3(MM * DD / 4 / 256, 1, 3), 256>>>(xq, xk, xv, Xhp, Xlp);
    cvt_w<<<dim3(DD * DD / 4 / 256, 1, 4), 256>>>(wq, wk, wv, wo, Whp, Wlp);

    tc_gemm_qkv<<<dim3(DD / 128, MM / 128, 3), 256, GEMM_SMEM_P>>>(
        Xhp, Xlp, Whp, Wlp, bq, bk, bv,
        Qp, Khp, Klp, Vhp, Vlp, mapp, cntp);

    attn_tc<<<dim3(SS / 128, HH, BB), 256, ATTN_SMEM>>>(
        Qp, Khp, Klp, Vhp, Vlp, cntp, Ahp, Alp);

    tc_gemm_out<<<dim3(DD / 128, MM / 128), 256, GEMM_SMEM_P>>>(
        Ahp, Alp, Whp, Wlp, bo, out);
}